// round 3
// baseline (speedup 1.0000x reference)
#include <cuda_runtime.h>
#include <math.h>

#define NTH 256
#define TW  128           // outputs per block

constexpr int NTOT = 2097152;
constexpr int NOUT = NTOT - 6;
constexpr int ST   = 136; // activation row stride (floats), 16B-aligned

// ---- constant-memory weight offsets (floats) ----
constexpr int O_W1 = 0;            // 100
constexpr int O_B1 = 100;          // 20
constexpr int O_W2 = 120;          // 4000
constexpr int O_B2 = 4120;         // 40
constexpr int O_W3 = 4160;         // 3200
constexpr int O_B3 = 7360;         // 80
constexpr int O_W4 = 7440;         // 3200
constexpr int O_B4 = 10640;        // 40
constexpr int O_W5 = 10680;        // 2400
constexpr int O_B5 = 13080;        // 20
constexpr int O_W6 = 13100;        // 20
constexpr int O_B6 = 13120;        // 1
__constant__ float cw[13124];

// ---- shared-memory layout (floats) ----
// X buffer (80 rows): A1 (rows 0-19), then A3 (80 rows), then A5 (rows 0-19)
// Y buffer (40 rows): A2, then A4
constexpr int O_UU  = 0;             // 144  (uu window: [o0-4, o0+TW+10))
constexpr int O_DIF = 144;           // 144  (dif window: [o0-3, o0+TW+9))
constexpr int O_BM  = 288;           // 136  (base o0+2)
constexpr int O_Y   = 424;           // 40*ST
constexpr int O_X   = O_Y + 40 * ST; // 80*ST
constexpr int SMEM_FLOATS = O_X + 80 * ST;
constexpr int SMEM_BYTES  = SMEM_FLOATS * 4;   // ~67 KB

__device__ __forceinline__ float eluf(float x) {
    return x > 0.f ? x : (__expf(x) - 1.f);
}

__device__ __forceinline__ float weno_side(float u0, float u1, float u2, float u3, float u4,
                                           float m0, float m1, float m2, float e) {
    const float c16 = 1.f / 6.f;
    float f0 = (11.f * u2 - 7.f * u3 + 2.f * u4) * c16;
    float f1 = (2.f * u1 + 5.f * u2 - u3) * c16;
    float f2 = (-u0 + 5.f * u1 + 2.f * u2) * c16;
    float t, b0, b1, b2;
    t = u2 - 2.f * u3 + u4;          b0 = (13.f / 12.f) * t * t;
    t = 3.f * u2 - 4.f * u3 + u4;    b0 += 0.25f * t * t;
    t = u1 - 2.f * u2 + u3;          b1 = (13.f / 12.f) * t * t;
    t = u1 - u3;                     b1 += 0.25f * t * t;
    t = u0 - 2.f * u1 + u2;          b2 = (13.f / 12.f) * t * t;
    t = u0 - 4.f * u1 + 3.f * u2;    b2 += 0.25f * t * t;
    b0 *= m0; b1 *= m1; b2 *= m2;
    float brs = (b2 - b0) * (b2 - b0);
    float q0 = (e + b0) * (e + b0);
    float q1 = (e + b1) * (e + b1);
    float q2 = (e + b2) * (e + b2);
    float o0 = 0.1f / q0 * (brs + q0);
    float o1 = 0.6f / q1 * (brs + q1);
    float o2 = 0.3f / q2 * (brs + q2);
    float s = o0 + o1 + o2;
    return (o0 * f0 + o1 * f1 + o2 * f2) / s;
}

__global__ __launch_bounds__(NTH, 3)
void weno_fused(const float* __restrict__ uu, const float* __restrict__ e_p,
                float* __restrict__ out) {
    extern __shared__ float sm[];
    const int tid = threadIdx.x;
    const int o0 = blockIdx.x * TW;

    // ---- stage uu window [o0-4, o0+TW+10), index-clamped ----
    for (int i = tid; i < TW + 14; i += NTH) {
        int g = o0 - 4 + i;
        g = min(max(g, 0), NTOT - 1);
        sm[O_UU + i] = uu[g];
    }
    __syncthreads();

    // ---- dif window [o0-3, o0+TW+9); zero outside [0,N) ----
    for (int i = tid; i < TW + 12; i += NTH) {
        int gi = o0 - 3 + i;
        float v = 0.f;
        if ((unsigned)gi < (unsigned)NTOT) {
            int m1 = min(gi, NTOT - 2);
            int m2 = max(gi - 1, 0);
            int base = o0 - 4;
            v = 0.5f * ((sm[O_UU + m1 + 1 - base] - sm[O_UU + m1 - base]) +
                        (sm[O_UU + m2 + 1 - base] - sm[O_UU + m2 - base]));
        }
        sm[O_DIF + i] = v;
    }
    __syncthreads();

    // ---- conv1: 1->20, k5 pad2.  A1 = X rows 0-19, base o0-1 ----
    for (int t = tid; t < 20 * 34; t += NTH) {
        int c = t / 34, x0 = (t % 34) * 4;
        float bias = cw[O_B1 + c];
        float c0 = bias, c1 = bias, c2 = bias, c3 = bias;
        float4 d0 = *(const float4*)&sm[O_DIF + x0];
        float4 d1 = *(const float4*)&sm[O_DIF + x0 + 4];
        float win[8] = {d0.x, d0.y, d0.z, d0.w, d1.x, d1.y, d1.z, d1.w};
        #pragma unroll
        for (int k = 0; k < 5; k++) {
            float w = cw[O_W1 + c * 5 + k];
            c0 += w * win[k]; c1 += w * win[k + 1];
            c2 += w * win[k + 2]; c3 += w * win[k + 3];
        }
        int p = o0 - 1 + x0;
        float4 r;
        r.x = (unsigned)(p + 0) < (unsigned)NTOT ? eluf(c0) : 0.f;
        r.y = (unsigned)(p + 1) < (unsigned)NTOT ? eluf(c1) : 0.f;
        r.z = (unsigned)(p + 2) < (unsigned)NTOT ? eluf(c2) : 0.f;
        r.w = (unsigned)(p + 3) < (unsigned)NTOT ? eluf(c3) : 0.f;
        *(float4*)&sm[O_X + c * ST + x0] = r;
    }
    __syncthreads();

    // ---- conv2: 20->40, k5 pad2.  2 oc x 8 pos.  reads X(A1) -> writes Y(A2), base o0+1 ----
    for (int t = tid; t < 20 * 17; t += NTH) {
        int ocp = t / 17, oct = t % 17;
        int x0 = oct * 8;
        int oc0 = ocp * 2;
        float bA = cw[O_B2 + oc0], bB = cw[O_B2 + oc0 + 1];
        float aA[8], aB[8];
        #pragma unroll
        for (int p = 0; p < 8; p++) { aA[p] = bA; aB[p] = bB; }
        #pragma unroll 4
        for (int ic = 0; ic < 20; ic++) {
            const float* ar = &sm[O_X + ic * ST + x0];
            float4 v0 = *(const float4*)(ar);
            float4 v1 = *(const float4*)(ar + 4);
            float4 v2 = *(const float4*)(ar + 8);
            float win[12] = {v0.x, v0.y, v0.z, v0.w, v1.x, v1.y, v1.z, v1.w,
                             v2.x, v2.y, v2.z, v2.w};
            #pragma unroll
            for (int k = 0; k < 5; k++) {
                float a = cw[O_W2 + (oc0 * 20 + ic) * 5 + k];
                float b = cw[O_W2 + ((oc0 + 1) * 20 + ic) * 5 + k];
                #pragma unroll
                for (int p = 0; p < 8; p++) {
                    aA[p] += a * win[p + k];
                    aB[p] += b * win[p + k];
                }
            }
        }
        float* dA = &sm[O_Y + oc0 * ST + x0];
        float* dB = dA + ST;
        float4 rA0, rA1, rB0, rB1;
        rA0.x = eluf(aA[0]); rA0.y = eluf(aA[1]); rA0.z = eluf(aA[2]); rA0.w = eluf(aA[3]);
        rA1.x = eluf(aA[4]); rA1.y = eluf(aA[5]); rA1.z = eluf(aA[6]); rA1.w = eluf(aA[7]);
        rB0.x = eluf(aB[0]); rB0.y = eluf(aB[1]); rB0.z = eluf(aB[2]); rB0.w = eluf(aB[3]);
        rB1.x = eluf(aB[4]); rB1.y = eluf(aB[5]); rB1.z = eluf(aB[6]); rB1.w = eluf(aB[7]);
        *(float4*)(dA) = rA0; *(float4*)(dA + 4) = rA1;
        *(float4*)(dB) = rB0; *(float4*)(dB + 4) = rB1;
    }
    __syncthreads();

    // ---- conv3: 40->80, 1x1.  4 oc x 4 pos.  reads Y(A2) -> writes X(A3) ----
    for (int t = tid; t < 20 * 33; t += NTH) {
        int ocq = t / 33, xq = t % 33;
        int x0 = xq * 4;
        int oc0 = ocq * 4;
        float a0[4], a1[4], a2[4], a3[4];
        {
            float q0 = cw[O_B3 + oc0], q1 = cw[O_B3 + oc0 + 1];
            float q2 = cw[O_B3 + oc0 + 2], q3 = cw[O_B3 + oc0 + 3];
            #pragma unroll
            for (int p = 0; p < 4; p++) { a0[p] = q0; a1[p] = q1; a2[p] = q2; a3[p] = q3; }
        }
        #pragma unroll 8
        for (int ic = 0; ic < 40; ic++) {
            float4 v = *(const float4*)&sm[O_Y + ic * ST + x0];
            float w0 = cw[O_W3 + (oc0 + 0) * 40 + ic];
            float w1_ = cw[O_W3 + (oc0 + 1) * 40 + ic];
            float w2_ = cw[O_W3 + (oc0 + 2) * 40 + ic];
            float w3_ = cw[O_W3 + (oc0 + 3) * 40 + ic];
            a0[0] += w0 * v.x; a0[1] += w0 * v.y; a0[2] += w0 * v.z; a0[3] += w0 * v.w;
            a1[0] += w1_ * v.x; a1[1] += w1_ * v.y; a1[2] += w1_ * v.z; a1[3] += w1_ * v.w;
            a2[0] += w2_ * v.x; a2[1] += w2_ * v.y; a2[2] += w2_ * v.z; a2[3] += w2_ * v.w;
            a3[0] += w3_ * v.x; a3[1] += w3_ * v.y; a3[2] += w3_ * v.z; a3[3] += w3_ * v.w;
        }
        float* d0 = &sm[O_X + oc0 * ST + x0];
        float4 r;
        r.x = eluf(a0[0]); r.y = eluf(a0[1]); r.z = eluf(a0[2]); r.w = eluf(a0[3]);
        *(float4*)(d0) = r;
        r.x = eluf(a1[0]); r.y = eluf(a1[1]); r.z = eluf(a1[2]); r.w = eluf(a1[3]);
        *(float4*)(d0 + ST) = r;
        r.x = eluf(a2[0]); r.y = eluf(a2[1]); r.z = eluf(a2[2]); r.w = eluf(a2[3]);
        *(float4*)(d0 + 2 * ST) = r;
        r.x = eluf(a3[0]); r.y = eluf(a3[1]); r.z = eluf(a3[2]); r.w = eluf(a3[3]);
        *(float4*)(d0 + 3 * ST) = r;
    }
    __syncthreads();

    // ---- conv4: 80->40, 1x1.  4 oc x 4 pos.  reads X(A3) -> writes Y(A4); zero outside [0,N) ----
    for (int t = tid; t < 10 * 33; t += NTH) {
        int ocq = t / 33, xq = t % 33;
        int x0 = xq * 4;
        int oc0 = ocq * 4;
        float a0[4], a1[4], a2[4], a3[4];
        {
            float q0 = cw[O_B4 + oc0], q1 = cw[O_B4 + oc0 + 1];
            float q2 = cw[O_B4 + oc0 + 2], q3 = cw[O_B4 + oc0 + 3];
            #pragma unroll
            for (int p = 0; p < 4; p++) { a0[p] = q0; a1[p] = q1; a2[p] = q2; a3[p] = q3; }
        }
        #pragma unroll 8
        for (int ic = 0; ic < 80; ic++) {
            float4 v = *(const float4*)&sm[O_X + ic * ST + x0];
            float w0 = cw[O_W4 + (oc0 + 0) * 80 + ic];
            float w1_ = cw[O_W4 + (oc0 + 1) * 80 + ic];
            float w2_ = cw[O_W4 + (oc0 + 2) * 80 + ic];
            float w3_ = cw[O_W4 + (oc0 + 3) * 80 + ic];
            a0[0] += w0 * v.x; a0[1] += w0 * v.y; a0[2] += w0 * v.z; a0[3] += w0 * v.w;
            a1[0] += w1_ * v.x; a1[1] += w1_ * v.y; a1[2] += w1_ * v.z; a1[3] += w1_ * v.w;
            a2[0] += w2_ * v.x; a2[1] += w2_ * v.y; a2[2] += w2_ * v.z; a2[3] += w2_ * v.w;
            a3[0] += w3_ * v.x; a3[1] += w3_ * v.y; a3[2] += w3_ * v.z; a3[3] += w3_ * v.w;
        }
        int p0 = o0 + 1 + x0;
        float m0 = (unsigned)(p0 + 0) < (unsigned)NTOT ? 1.f : 0.f;
        float m1 = (unsigned)(p0 + 1) < (unsigned)NTOT ? 1.f : 0.f;
        float m2 = (unsigned)(p0 + 2) < (unsigned)NTOT ? 1.f : 0.f;
        float m3 = (unsigned)(p0 + 3) < (unsigned)NTOT ? 1.f : 0.f;
        float* d0 = &sm[O_Y + oc0 * ST + x0];
        float4 r;
        r.x = m0 * eluf(a0[0]); r.y = m1 * eluf(a0[1]); r.z = m2 * eluf(a0[2]); r.w = m3 * eluf(a0[3]);
        *(float4*)(d0) = r;
        r.x = m0 * eluf(a1[0]); r.y = m1 * eluf(a1[1]); r.z = m2 * eluf(a1[2]); r.w = m3 * eluf(a1[3]);
        *(float4*)(d0 + ST) = r;
        r.x = m0 * eluf(a2[0]); r.y = m1 * eluf(a2[1]); r.z = m2 * eluf(a2[2]); r.w = m3 * eluf(a2[3]);
        *(float4*)(d0 + 2 * ST) = r;
        r.x = m0 * eluf(a3[0]); r.y = m1 * eluf(a3[1]); r.z = m2 * eluf(a3[2]); r.w = m3 * eluf(a3[3]);
        *(float4*)(d0 + 3 * ST) = r;
    }
    // zero A4 tail slots (read by conv5 sliding window at the tile edge)
    for (int t = tid; t < 40; t += NTH) {
        float4 z = {0.f, 0.f, 0.f, 0.f};
        *(float4*)&sm[O_Y + t * ST + 132] = z;
    }
    __syncthreads();

    // ---- conv5: 40->20, k3 pad1.  2 oc x 8 pos.  reads Y(A4) -> writes X(A5), base o0+2 ----
    for (int t = tid; t < 10 * 17; t += NTH) {
        int ocp = t / 17, oct = t % 17;
        int x0 = oct * 8;
        int oc0 = ocp * 2;
        float bA = cw[O_B5 + oc0], bB = cw[O_B5 + oc0 + 1];
        float aA[8], aB[8];
        #pragma unroll
        for (int p = 0; p < 8; p++) { aA[p] = bA; aB[p] = bB; }
        #pragma unroll 4
        for (int ic = 0; ic < 40; ic++) {
            const float* ar = &sm[O_Y + ic * ST + x0];
            float4 v0 = *(const float4*)(ar);
            float4 v1 = *(const float4*)(ar + 4);
            float4 v2 = *(const float4*)(ar + 8);
            float win[12] = {v0.x, v0.y, v0.z, v0.w, v1.x, v1.y, v1.z, v1.w,
                             v2.x, v2.y, v2.z, v2.w};
            #pragma unroll
            for (int k = 0; k < 3; k++) {
                float a = cw[O_W5 + (oc0 * 40 + ic) * 3 + k];
                float b = cw[O_W5 + ((oc0 + 1) * 40 + ic) * 3 + k];
                #pragma unroll
                for (int p = 0; p < 8; p++) {
                    aA[p] += a * win[p + k];
                    aB[p] += b * win[p + k];
                }
            }
        }
        float* dA = &sm[O_X + oc0 * ST + x0];
        float* dB = dA + ST;
        float4 rA0, rA1, rB0, rB1;
        rA0.x = eluf(aA[0]); rA0.y = eluf(aA[1]); rA0.z = eluf(aA[2]); rA0.w = eluf(aA[3]);
        rA1.x = eluf(aA[4]); rA1.y = eluf(aA[5]); rA1.z = eluf(aA[6]); rA1.w = eluf(aA[7]);
        rB0.x = eluf(aB[0]); rB0.y = eluf(aB[1]); rB0.z = eluf(aB[2]); rB0.w = eluf(aB[3]);
        rB1.x = eluf(aB[4]); rB1.y = eluf(aB[5]); rB1.z = eluf(aB[6]); rB1.w = eluf(aB[7]);
        *(float4*)(dA) = rA0; *(float4*)(dA + 4) = rA1;
        *(float4*)(dB) = rB0; *(float4*)(dB + 4) = rB1;
    }
    __syncthreads();

    // ---- conv6 + sigmoid + bias: beta_mult, base o0+2, width TW+2 ----
    for (int x = tid; x < TW + 2; x += NTH) {
        float acc = cw[O_B6];
        #pragma unroll
        for (int c = 0; c < 20; c++) acc += cw[O_W6 + c] * sm[O_X + c * ST + x];
        sm[O_BM + x] = 1.f / (1.f + __expf(-acc)) + 0.1f;
    }
    __syncthreads();

    // ---- WENO5 flux ----
    int j = o0 + tid;
    if (tid < TW && j < NOUT) {
        const float* U = &sm[O_UU + tid + 5];   // uu[j+1 .. j+6]
        float v0 = U[0], v1 = U[1], v2 = U[2], v3 = U[3], v4 = U[4], v5 = U[5];
        float m0 = sm[O_BM + tid];
        float m1 = sm[O_BM + tid + 1];
        float m2 = sm[O_BM + tid + 2];
        float e = e_p[0];
        float fluxp = weno_side(v1, v2, v3, v4, v5, m0, m1, m2, e);
        float fluxn = weno_side(v0, v1, v2, v3, v4, m0, m1, m2, e);
        out[j] = fluxp - fluxn;
    }
}

extern "C" void kernel_launch(void* const* d_in, const int* in_sizes, int n_in,
                              void* d_out, int out_size) {
    const float* uu = (const float*)d_in[0];
    const float* e  = (const float*)d_in[1];
    float* out = (float*)d_out;

    // stage weights into constant memory (graph-capturable D2D memcpy nodes)
    cudaMemcpyToSymbolAsync(cw, d_in[2],  100  * 4, O_W1 * 4, cudaMemcpyDeviceToDevice);
    cudaMemcpyToSymbolAsync(cw, d_in[3],  20   * 4, O_B1 * 4, cudaMemcpyDeviceToDevice);
    cudaMemcpyToSymbolAsync(cw, d_in[4],  4000 * 4, O_W2 * 4, cudaMemcpyDeviceToDevice);
    cudaMemcpyToSymbolAsync(cw, d_in[5],  40   * 4, O_B2 * 4, cudaMemcpyDeviceToDevice);
    cudaMemcpyToSymbolAsync(cw, d_in[6],  3200 * 4, O_W3 * 4, cudaMemcpyDeviceToDevice);
    cudaMemcpyToSymbolAsync(cw, d_in[7],  80   * 4, O_B3 * 4, cudaMemcpyDeviceToDevice);
    cudaMemcpyToSymbolAsync(cw, d_in[8],  3200 * 4, O_W4 * 4, cudaMemcpyDeviceToDevice);
    cudaMemcpyToSymbolAsync(cw, d_in[9],  40   * 4, O_B4 * 4, cudaMemcpyDeviceToDevice);
    cudaMemcpyToSymbolAsync(cw, d_in[10], 2400 * 4, O_W5 * 4, cudaMemcpyDeviceToDevice);
    cudaMemcpyToSymbolAsync(cw, d_in[11], 20   * 4, O_B5 * 4, cudaMemcpyDeviceToDevice);
    cudaMemcpyToSymbolAsync(cw, d_in[12], 20   * 4, O_W6 * 4, cudaMemcpyDeviceToDevice);
    cudaMemcpyToSymbolAsync(cw, d_in[13], 1    * 4, O_B6 * 4, cudaMemcpyDeviceToDevice);

    cudaFuncSetAttribute(weno_fused, cudaFuncAttributeMaxDynamicSharedMemorySize, SMEM_BYTES);
    int grid = (NOUT + TW - 1) / TW;
    weno_fused<<<grid, NTH, SMEM_BYTES>>>(uu, e, out);
}

// round 4
// speedup vs baseline: 6.7595x; 6.7595x over previous
#include <cuda_runtime.h>
#include <math.h>

#define NTH 512
#define TW  256           // outputs per block

constexpr int NTOT = 2097152;
constexpr int NOUT = NTOT - 6;
constexpr int ST2  = TW + 8;   // 264: activation row stride (floats), 16B-aligned

// ---- shared-memory weight offsets (floats) ----
constexpr int O_W1  = 0;                 // 100
constexpr int O_B1  = 100;               // 20
constexpr int O_W2p = 120;               // 40*20*8 = 6400 (padded stride 8, k in [0,5))
constexpr int O_B2  = O_W2p + 6400;      // 40
constexpr int O_W3  = O_B2 + 40;         // 3200
constexpr int O_B3  = O_W3 + 3200;       // 80
constexpr int O_W4  = O_B3 + 80;         // 3200
constexpr int O_B4  = O_W4 + 3200;       // 40
constexpr int O_W5p = O_B4 + 40;         // 20*40*4 = 3200 (padded stride 4, k in [0,3))
constexpr int O_B5  = O_W5p + 3200;      // 20
constexpr int O_W6  = O_B5 + 20;         // 20
constexpr int O_B6  = O_W6 + 20;         // 1 (+3 pad)
// ---- activation area ----
constexpr int O_UU  = O_B6 + 4;          // TW+14 = 270 -> alloc 272
constexpr int O_DIF = O_UU + 272;        // TW+12 = 268 -> alloc 272
constexpr int O_BM  = O_DIF + 272;       // TW+2 valid -> alloc 264
constexpr int O_Y   = O_BM + 264;        // 40*ST2  (A2, A4)
constexpr int O_X   = O_Y + 40 * ST2;    // 80*ST2  (A1 rows 0-19, A3 all, A5 rows 0-19)
constexpr int SMEM_FLOATS = O_X + 80 * ST2;
constexpr int SMEM_BYTES  = SMEM_FLOATS * 4;   // ~191 KB

__device__ __forceinline__ float eluf(float x) {
    return x > 0.f ? x : (__expf(x) - 1.f);
}

__device__ __forceinline__ float weno_side(float u0, float u1, float u2, float u3, float u4,
                                           float m0, float m1, float m2, float e) {
    const float c16 = 1.f / 6.f;
    float f0 = (11.f * u2 - 7.f * u3 + 2.f * u4) * c16;
    float f1 = (2.f * u1 + 5.f * u2 - u3) * c16;
    float f2 = (-u0 + 5.f * u1 + 2.f * u2) * c16;
    float t, b0, b1, b2;
    t = u2 - 2.f * u3 + u4;          b0 = (13.f / 12.f) * t * t;
    t = 3.f * u2 - 4.f * u3 + u4;    b0 += 0.25f * t * t;
    t = u1 - 2.f * u2 + u3;          b1 = (13.f / 12.f) * t * t;
    t = u1 - u3;                     b1 += 0.25f * t * t;
    t = u0 - 2.f * u1 + u2;          b2 = (13.f / 12.f) * t * t;
    t = u0 - 4.f * u1 + 3.f * u2;    b2 += 0.25f * t * t;
    b0 *= m0; b1 *= m1; b2 *= m2;
    float brs = (b2 - b0) * (b2 - b0);
    float q0 = (e + b0) * (e + b0);
    float q1 = (e + b1) * (e + b1);
    float q2 = (e + b2) * (e + b2);
    float o0 = 0.1f / q0 * (brs + q0);
    float o1 = 0.6f / q1 * (brs + q1);
    float o2 = 0.3f / q2 * (brs + q2);
    float s = o0 + o1 + o2;
    return (o0 * f0 + o1 * f1 + o2 * f2) / s;
}

__global__ __launch_bounds__(NTH, 1)
void weno_fused(const float* __restrict__ uu, const float* __restrict__ e_p,
                const float* __restrict__ w1, const float* __restrict__ b1,
                const float* __restrict__ w2, const float* __restrict__ b2,
                const float* __restrict__ w3, const float* __restrict__ b3,
                const float* __restrict__ w4, const float* __restrict__ b4,
                const float* __restrict__ w5, const float* __restrict__ b5,
                const float* __restrict__ w6, const float* __restrict__ b6,
                float* __restrict__ out) {
    extern __shared__ float sm[];
    const int tid = threadIdx.x;
    const int o0 = blockIdx.x * TW;

    // ---- stage weights (W2 padded to stride 8, W5 to stride 4) ----
    for (int i = tid; i < 100;  i += NTH) sm[O_W1 + i] = w1[i];
    for (int i = tid; i < 20;   i += NTH) sm[O_B1 + i] = b1[i];
    for (int i = tid; i < 4000; i += NTH) sm[O_W2p + (i / 5) * 8 + (i % 5)] = w2[i];
    for (int i = tid; i < 40;   i += NTH) sm[O_B2 + i] = b2[i];
    for (int i = tid; i < 3200; i += NTH) sm[O_W3 + i] = w3[i];
    for (int i = tid; i < 80;   i += NTH) sm[O_B3 + i] = b3[i];
    for (int i = tid; i < 3200; i += NTH) sm[O_W4 + i] = w4[i];
    for (int i = tid; i < 40;   i += NTH) sm[O_B4 + i] = b4[i];
    for (int i = tid; i < 2400; i += NTH) sm[O_W5p + (i / 3) * 4 + (i % 3)] = w5[i];
    for (int i = tid; i < 20;   i += NTH) sm[O_B5 + i] = b5[i];
    for (int i = tid; i < 20;   i += NTH) sm[O_W6 + i] = w6[i];
    if (tid == 0) sm[O_B6] = b6[0];

    // ---- stage uu window [o0-4, o0+TW+10), index-clamped ----
    for (int i = tid; i < TW + 14; i += NTH) {
        int g = o0 - 4 + i;
        g = min(max(g, 0), NTOT - 1);
        sm[O_UU + i] = uu[g];
    }
    __syncthreads();

    // ---- dif window [o0-3, o0+TW+9); zero outside [0,N) ----
    for (int i = tid; i < TW + 12; i += NTH) {
        int gi = o0 - 3 + i;
        float v = 0.f;
        if ((unsigned)gi < (unsigned)NTOT) {
            int m1 = min(gi, NTOT - 2);
            int m2 = max(gi - 1, 0);
            int base = o0 - 4;
            v = 0.5f * ((sm[O_UU + m1 + 1 - base] - sm[O_UU + m1 - base]) +
                        (sm[O_UU + m2 + 1 - base] - sm[O_UU + m2 - base]));
        }
        sm[O_DIF + i] = v;
    }
    __syncthreads();

    // ---- conv1: 1->20, k5 pad2.  A1 = X rows 0-19, base o0-1, width TW+8 (66 quads) ----
    for (int t = tid; t < 20 * 66; t += NTH) {
        int c = t / 66, x0 = (t % 66) * 4;
        float bias = sm[O_B1 + c];
        float c0 = bias, c1 = bias, c2 = bias, c3 = bias;
        float4 d0 = *(const float4*)&sm[O_DIF + x0];
        float4 d1 = *(const float4*)&sm[O_DIF + x0 + 4];
        float win[8] = {d0.x, d0.y, d0.z, d0.w, d1.x, d1.y, d1.z, d1.w};
        #pragma unroll
        for (int k = 0; k < 5; k++) {
            float w = sm[O_W1 + c * 5 + k];
            c0 += w * win[k]; c1 += w * win[k + 1];
            c2 += w * win[k + 2]; c3 += w * win[k + 3];
        }
        int p = o0 - 1 + x0;
        float4 r;
        r.x = (unsigned)(p + 0) < (unsigned)NTOT ? eluf(c0) : 0.f;
        r.y = (unsigned)(p + 1) < (unsigned)NTOT ? eluf(c1) : 0.f;
        r.z = (unsigned)(p + 2) < (unsigned)NTOT ? eluf(c2) : 0.f;
        r.w = (unsigned)(p + 3) < (unsigned)NTOT ? eluf(c3) : 0.f;
        *(float4*)&sm[O_X + c * ST2 + x0] = r;
    }
    __syncthreads();

    // ---- conv2: 20->40, k5 pad2.  2 oc x 8 pos.  X(A1) -> Y(A2), base o0+1, 33 chunks ----
    for (int t = tid; t < 20 * 33; t += NTH) {
        int ocp = t / 33, oct = t % 33;
        int x0 = oct * 8;
        int oc0 = ocp * 2;
        float bA = sm[O_B2 + oc0], bB = sm[O_B2 + oc0 + 1];
        float aA[8], aB[8];
        #pragma unroll
        for (int p = 0; p < 8; p++) { aA[p] = bA; aB[p] = bB; }
        #pragma unroll 4
        for (int ic = 0; ic < 20; ic++) {
            const float* ar = &sm[O_X + ic * ST2 + x0];
            float4 v0 = *(const float4*)(ar);
            float4 v1 = *(const float4*)(ar + 4);
            float4 v2 = *(const float4*)(ar + 8);
            float win[12] = {v0.x, v0.y, v0.z, v0.w, v1.x, v1.y, v1.z, v1.w,
                             v2.x, v2.y, v2.z, v2.w};
            float4 wa = *(const float4*)&sm[O_W2p + (oc0 * 20 + ic) * 8];
            float  wa4 = sm[O_W2p + (oc0 * 20 + ic) * 8 + 4];
            float4 wb = *(const float4*)&sm[O_W2p + ((oc0 + 1) * 20 + ic) * 8];
            float  wb4 = sm[O_W2p + ((oc0 + 1) * 20 + ic) * 8 + 4];
            float wka[5] = {wa.x, wa.y, wa.z, wa.w, wa4};
            float wkb[5] = {wb.x, wb.y, wb.z, wb.w, wb4};
            #pragma unroll
            for (int k = 0; k < 5; k++) {
                #pragma unroll
                for (int p = 0; p < 8; p++) {
                    aA[p] += wka[k] * win[p + k];
                    aB[p] += wkb[k] * win[p + k];
                }
            }
        }
        float* dA = &sm[O_Y + oc0 * ST2 + x0];
        float* dB = dA + ST2;
        float4 rA0, rA1, rB0, rB1;
        rA0.x = eluf(aA[0]); rA0.y = eluf(aA[1]); rA0.z = eluf(aA[2]); rA0.w = eluf(aA[3]);
        rA1.x = eluf(aA[4]); rA1.y = eluf(aA[5]); rA1.z = eluf(aA[6]); rA1.w = eluf(aA[7]);
        rB0.x = eluf(aB[0]); rB0.y = eluf(aB[1]); rB0.z = eluf(aB[2]); rB0.w = eluf(aB[3]);
        rB1.x = eluf(aB[4]); rB1.y = eluf(aB[5]); rB1.z = eluf(aB[6]); rB1.w = eluf(aB[7]);
        *(float4*)(dA) = rA0; *(float4*)(dA + 4) = rA1;
        *(float4*)(dB) = rB0; *(float4*)(dB + 4) = rB1;
    }
    __syncthreads();

    // ---- conv3: 40->80, 1x1.  4 oc x 4 pos, ic blocked by 4.  Y(A2) -> X(A3), 65 quads ----
    for (int t = tid; t < 20 * 65; t += NTH) {
        int ocq = t / 65, xq = t % 65;
        int x0 = xq * 4;
        int oc0 = ocq * 4;
        float a0[4], a1[4], a2[4], a3[4];
        {
            float q0 = sm[O_B3 + oc0], q1 = sm[O_B3 + oc0 + 1];
            float q2 = sm[O_B3 + oc0 + 2], q3 = sm[O_B3 + oc0 + 3];
            #pragma unroll
            for (int p = 0; p < 4; p++) { a0[p] = q0; a1[p] = q1; a2[p] = q2; a3[p] = q3; }
        }
        #pragma unroll 2
        for (int ic = 0; ic < 40; ic += 4) {
            float4 w0 = *(const float4*)&sm[O_W3 + (oc0 + 0) * 40 + ic];
            float4 w1v = *(const float4*)&sm[O_W3 + (oc0 + 1) * 40 + ic];
            float4 w2v = *(const float4*)&sm[O_W3 + (oc0 + 2) * 40 + ic];
            float4 w3v = *(const float4*)&sm[O_W3 + (oc0 + 3) * 40 + ic];
            float4 v0 = *(const float4*)&sm[O_Y + (ic + 0) * ST2 + x0];
            float4 v1 = *(const float4*)&sm[O_Y + (ic + 1) * ST2 + x0];
            float4 v2 = *(const float4*)&sm[O_Y + (ic + 2) * ST2 + x0];
            float4 v3 = *(const float4*)&sm[O_Y + (ic + 3) * ST2 + x0];
            float vv[4][4] = {{v0.x, v0.y, v0.z, v0.w}, {v1.x, v1.y, v1.z, v1.w},
                              {v2.x, v2.y, v2.z, v2.w}, {v3.x, v3.y, v3.z, v3.w}};
            float ww0[4] = {w0.x, w0.y, w0.z, w0.w};
            float ww1[4] = {w1v.x, w1v.y, w1v.z, w1v.w};
            float ww2[4] = {w2v.x, w2v.y, w2v.z, w2v.w};
            float ww3[4] = {w3v.x, w3v.y, w3v.z, w3v.w};
            #pragma unroll
            for (int j = 0; j < 4; j++) {
                #pragma unroll
                for (int p = 0; p < 4; p++) {
                    a0[p] += ww0[j] * vv[j][p];
                    a1[p] += ww1[j] * vv[j][p];
                    a2[p] += ww2[j] * vv[j][p];
                    a3[p] += ww3[j] * vv[j][p];
                }
            }
        }
        float* d0 = &sm[O_X + oc0 * ST2 + x0];
        float4 r;
        r.x = eluf(a0[0]); r.y = eluf(a0[1]); r.z = eluf(a0[2]); r.w = eluf(a0[3]);
        *(float4*)(d0) = r;
        r.x = eluf(a1[0]); r.y = eluf(a1[1]); r.z = eluf(a1[2]); r.w = eluf(a1[3]);
        *(float4*)(d0 + ST2) = r;
        r.x = eluf(a2[0]); r.y = eluf(a2[1]); r.z = eluf(a2[2]); r.w = eluf(a2[3]);
        *(float4*)(d0 + 2 * ST2) = r;
        r.x = eluf(a3[0]); r.y = eluf(a3[1]); r.z = eluf(a3[2]); r.w = eluf(a3[3]);
        *(float4*)(d0 + 3 * ST2) = r;
    }
    __syncthreads();

    // ---- conv4: 80->40, 1x1.  4 oc x 4 pos, ic blocked by 4.  X(A3) -> Y(A4); zero outside [0,N) ----
    for (int t = tid; t < 10 * 65; t += NTH) {
        int ocq = t / 65, xq = t % 65;
        int x0 = xq * 4;
        int oc0 = ocq * 4;
        float a0[4], a1[4], a2[4], a3[4];
        {
            float q0 = sm[O_B4 + oc0], q1 = sm[O_B4 + oc0 + 1];
            float q2 = sm[O_B4 + oc0 + 2], q3 = sm[O_B4 + oc0 + 3];
            #pragma unroll
            for (int p = 0; p < 4; p++) { a0[p] = q0; a1[p] = q1; a2[p] = q2; a3[p] = q3; }
        }
        #pragma unroll 2
        for (int ic = 0; ic < 80; ic += 4) {
            float4 w0 = *(const float4*)&sm[O_W4 + (oc0 + 0) * 80 + ic];
            float4 w1v = *(const float4*)&sm[O_W4 + (oc0 + 1) * 80 + ic];
            float4 w2v = *(const float4*)&sm[O_W4 + (oc0 + 2) * 80 + ic];
            float4 w3v = *(const float4*)&sm[O_W4 + (oc0 + 3) * 80 + ic];
            float4 v0 = *(const float4*)&sm[O_X + (ic + 0) * ST2 + x0];
            float4 v1 = *(const float4*)&sm[O_X + (ic + 1) * ST2 + x0];
            float4 v2 = *(const float4*)&sm[O_X + (ic + 2) * ST2 + x0];
            float4 v3 = *(const float4*)&sm[O_X + (ic + 3) * ST2 + x0];
            float vv[4][4] = {{v0.x, v0.y, v0.z, v0.w}, {v1.x, v1.y, v1.z, v1.w},
                              {v2.x, v2.y, v2.z, v2.w}, {v3.x, v3.y, v3.z, v3.w}};
            float ww0[4] = {w0.x, w0.y, w0.z, w0.w};
            float ww1[4] = {w1v.x, w1v.y, w1v.z, w1v.w};
            float ww2[4] = {w2v.x, w2v.y, w2v.z, w2v.w};
            float ww3[4] = {w3v.x, w3v.y, w3v.z, w3v.w};
            #pragma unroll
            for (int j = 0; j < 4; j++) {
                #pragma unroll
                for (int p = 0; p < 4; p++) {
                    a0[p] += ww0[j] * vv[j][p];
                    a1[p] += ww1[j] * vv[j][p];
                    a2[p] += ww2[j] * vv[j][p];
                    a3[p] += ww3[j] * vv[j][p];
                }
            }
        }
        int p0 = o0 + 1 + x0;
        float m0 = (unsigned)(p0 + 0) < (unsigned)NTOT ? 1.f : 0.f;
        float m1 = (unsigned)(p0 + 1) < (unsigned)NTOT ? 1.f : 0.f;
        float m2 = (unsigned)(p0 + 2) < (unsigned)NTOT ? 1.f : 0.f;
        float m3 = (unsigned)(p0 + 3) < (unsigned)NTOT ? 1.f : 0.f;
        float* d0 = &sm[O_Y + oc0 * ST2 + x0];
        float4 r;
        r.x = m0 * eluf(a0[0]); r.y = m1 * eluf(a0[1]); r.z = m2 * eluf(a0[2]); r.w = m3 * eluf(a0[3]);
        *(float4*)(d0) = r;
        r.x = m0 * eluf(a1[0]); r.y = m1 * eluf(a1[1]); r.z = m2 * eluf(a1[2]); r.w = m3 * eluf(a1[3]);
        *(float4*)(d0 + ST2) = r;
        r.x = m0 * eluf(a2[0]); r.y = m1 * eluf(a2[1]); r.z = m2 * eluf(a2[2]); r.w = m3 * eluf(a2[3]);
        *(float4*)(d0 + 2 * ST2) = r;
        r.x = m0 * eluf(a3[0]); r.y = m1 * eluf(a3[1]); r.z = m2 * eluf(a3[2]); r.w = m3 * eluf(a3[3]);
        *(float4*)(d0 + 3 * ST2) = r;
    }
    // zero A4 tail slots (positions 260..263, read by conv5 window at the tile edge)
    for (int t = tid; t < 40; t += NTH) {
        float4 z = {0.f, 0.f, 0.f, 0.f};
        *(float4*)&sm[O_Y + t * ST2 + (TW + 4)] = z;
    }
    __syncthreads();

    // ---- conv5: 40->20, k3 pad1.  2 oc x 8 pos.  Y(A4) -> X(A5), base o0+2, 33 chunks ----
    for (int t = tid; t < 10 * 33; t += NTH) {
        int ocp = t / 33, oct = t % 33;
        int x0 = oct * 8;
        int oc0 = ocp * 2;
        float bA = sm[O_B5 + oc0], bB = sm[O_B5 + oc0 + 1];
        float aA[8], aB[8];
        #pragma unroll
        for (int p = 0; p < 8; p++) { aA[p] = bA; aB[p] = bB; }
        #pragma unroll 4
        for (int ic = 0; ic < 40; ic++) {
            const float* ar = &sm[O_Y + ic * ST2 + x0];
            float4 v0 = *(const float4*)(ar);
            float4 v1 = *(const float4*)(ar + 4);
            float4 v2 = *(const float4*)(ar + 8);
            float win[12] = {v0.x, v0.y, v0.z, v0.w, v1.x, v1.y, v1.z, v1.w,
                             v2.x, v2.y, v2.z, v2.w};
            float4 wa = *(const float4*)&sm[O_W5p + (oc0 * 40 + ic) * 4];
            float4 wb = *(const float4*)&sm[O_W5p + ((oc0 + 1) * 40 + ic) * 4];
            float wka[3] = {wa.x, wa.y, wa.z};
            float wkb[3] = {wb.x, wb.y, wb.z};
            #pragma unroll
            for (int k = 0; k < 3; k++) {
                #pragma unroll
                for (int p = 0; p < 8; p++) {
                    aA[p] += wka[k] * win[p + k];
                    aB[p] += wkb[k] * win[p + k];
                }
            }
        }
        float* dA = &sm[O_X + oc0 * ST2 + x0];
        float* dB = dA + ST2;
        float4 rA0, rA1, rB0, rB1;
        rA0.x = eluf(aA[0]); rA0.y = eluf(aA[1]); rA0.z = eluf(aA[2]); rA0.w = eluf(aA[3]);
        rA1.x = eluf(aA[4]); rA1.y = eluf(aA[5]); rA1.z = eluf(aA[6]); rA1.w = eluf(aA[7]);
        rB0.x = eluf(aB[0]); rB0.y = eluf(aB[1]); rB0.z = eluf(aB[2]); rB0.w = eluf(aB[3]);
        rB1.x = eluf(aB[4]); rB1.y = eluf(aB[5]); rB1.z = eluf(aB[6]); rB1.w = eluf(aB[7]);
        *(float4*)(dA) = rA0; *(float4*)(dA + 4) = rA1;
        *(float4*)(dB) = rB0; *(float4*)(dB + 4) = rB1;
    }
    __syncthreads();

    // ---- conv6 + sigmoid + bias: beta_mult, base o0+2, width TW+2 ----
    for (int x = tid; x < TW + 2; x += NTH) {
        float acc = sm[O_B6];
        #pragma unroll
        for (int c = 0; c < 20; c++) acc += sm[O_W6 + c] * sm[O_X + c * ST2 + x];
        sm[O_BM + x] = 1.f / (1.f + __expf(-acc)) + 0.1f;
    }
    __syncthreads();

    // ---- WENO5 flux ----
    int j = o0 + tid;
    if (tid < TW && j < NOUT) {
        const float* U = &sm[O_UU + tid + 5];   // uu[j+1 .. j+6]
        float v0 = U[0], v1 = U[1], v2 = U[2], v3 = U[3], v4 = U[4], v5 = U[5];
        float m0 = sm[O_BM + tid];
        float m1 = sm[O_BM + tid + 1];
        float m2 = sm[O_BM + tid + 2];
        float e = e_p[0];
        float fluxp = weno_side(v1, v2, v3, v4, v5, m0, m1, m2, e);
        float fluxn = weno_side(v0, v1, v2, v3, v4, m0, m1, m2, e);
        out[j] = fluxp - fluxn;
    }
}

extern "C" void kernel_launch(void* const* d_in, const int* in_sizes, int n_in,
                              void* d_out, int out_size) {
    const float* uu = (const float*)d_in[0];
    const float* e  = (const float*)d_in[1];
    const float* w1 = (const float*)d_in[2];
    const float* b1 = (const float*)d_in[3];
    const float* w2 = (const float*)d_in[4];
    const float* b2 = (const float*)d_in[5];
    const float* w3 = (const float*)d_in[6];
    const float* b3 = (const float*)d_in[7];
    const float* w4 = (const float*)d_in[8];
    const float* b4 = (const float*)d_in[9];
    const float* w5 = (const float*)d_in[10];
    const float* b5 = (const float*)d_in[11];
    const float* w6 = (const float*)d_in[12];
    const float* b6 = (const float*)d_in[13];
    float* out = (float*)d_out;

    cudaFuncSetAttribute(weno_fused, cudaFuncAttributeMaxDynamicSharedMemorySize, SMEM_BYTES);
    int grid = (NOUT + TW - 1) / TW;
    weno_fused<<<grid, NTH, SMEM_BYTES>>>(uu, e, w1, b1, w2, b2, w3, b3, w4, b4,
                                          w5, b5, w6, b6, out);
}

// round 5
// speedup vs baseline: 6.8691x; 1.0162x over previous
#include <cuda_runtime.h>
#include <math.h>

#define NTH 640
#define TW  256           // outputs per block

constexpr int NTOT = 2097152;
constexpr int NOUT = NTOT - 6;
constexpr int ST2  = TW + 8;   // 264: activation row stride (floats), 16B-aligned

// ---- shared-memory weight offsets (floats); transposed oc-contiguous layouts ----
constexpr int O_W1  = 0;                 // 100   w1[oc][k] (as-is)
constexpr int O_B1  = 100;               // 20
constexpr int O_W2T = 120;               // 4000  T2[(ic*5+k)*40 + oc]
constexpr int O_B2  = 4120;              // 40
constexpr int O_W3T = 4160;              // 3200  T3[ic*80 + oc]
constexpr int O_B3  = 7360;              // 80
constexpr int O_W4T = 7440;              // 3200  T4[ic*40 + oc]
constexpr int O_B4  = 10640;             // 40
constexpr int O_W5T = 10680;             // 2400  T5[(ic*3+k)*20 + oc]
constexpr int O_B5  = 13080;             // 20
constexpr int O_W6  = 13100;             // 20
constexpr int O_B6  = 13120;             // 1 (+3 pad)
// ---- activation area ----
constexpr int O_UU  = 13124;             // 272 alloc (need TW+14)
constexpr int O_DIF = O_UU + 272;        // 272 alloc (need TW+12)
constexpr int O_BM  = O_DIF + 272;       // 264 alloc (need TW+2)
constexpr int O_Y   = O_BM + 264;        // 40*ST2  (A2, A4)
constexpr int O_X   = O_Y + 40 * ST2;    // 80*ST2  (A1 rows 0-19, A3 all, A5 rows 0-19)
constexpr int SMEM_FLOATS = O_X + 80 * ST2;
constexpr int SMEM_BYTES  = SMEM_FLOATS * 4;   // ~178 KB

__device__ __forceinline__ float eluf(float x) {
    return x > 0.f ? x : (__expf(x) - 1.f);
}

__device__ __forceinline__ float weno_side(float u0, float u1, float u2, float u3, float u4,
                                           float m0, float m1, float m2, float e) {
    const float c16 = 1.f / 6.f;
    float f0 = (11.f * u2 - 7.f * u3 + 2.f * u4) * c16;
    float f1 = (2.f * u1 + 5.f * u2 - u3) * c16;
    float f2 = (-u0 + 5.f * u1 + 2.f * u2) * c16;
    float t, b0, b1, b2;
    t = u2 - 2.f * u3 + u4;          b0 = (13.f / 12.f) * t * t;
    t = 3.f * u2 - 4.f * u3 + u4;    b0 += 0.25f * t * t;
    t = u1 - 2.f * u2 + u3;          b1 = (13.f / 12.f) * t * t;
    t = u1 - u3;                     b1 += 0.25f * t * t;
    t = u0 - 2.f * u1 + u2;          b2 = (13.f / 12.f) * t * t;
    t = u0 - 4.f * u1 + 3.f * u2;    b2 += 0.25f * t * t;
    b0 *= m0; b1 *= m1; b2 *= m2;
    float brs = (b2 - b0) * (b2 - b0);
    float q0 = (e + b0) * (e + b0);
    float q1 = (e + b1) * (e + b1);
    float q2 = (e + b2) * (e + b2);
    float o0 = 0.1f / q0 * (brs + q0);
    float o1 = 0.6f / q1 * (brs + q1);
    float o2 = 0.3f / q2 * (brs + q2);
    float s = o0 + o1 + o2;
    return (o0 * f0 + o1 * f1 + o2 * f2) / s;
}

__global__ __launch_bounds__(NTH, 1)
void weno_fused(const float* __restrict__ uu, const float* __restrict__ e_p,
                const float* __restrict__ w1, const float* __restrict__ b1,
                const float* __restrict__ w2, const float* __restrict__ b2,
                const float* __restrict__ w3, const float* __restrict__ b3,
                const float* __restrict__ w4, const float* __restrict__ b4,
                const float* __restrict__ w5, const float* __restrict__ b5,
                const float* __restrict__ w6, const float* __restrict__ b6,
                float* __restrict__ out) {
    extern __shared__ float sm[];
    const int tid = threadIdx.x;
    const int o0 = blockIdx.x * TW;

    // ---- stage weights (transposed to oc-contiguous) ----
    for (int i = tid; i < 100;  i += NTH) sm[O_W1 + i] = w1[i];
    for (int i = tid; i < 20;   i += NTH) sm[O_B1 + i] = b1[i];
    for (int i = tid; i < 4000; i += NTH) {
        int oc = i / 100, r = i % 100;           // r = ic*5 + k
        sm[O_W2T + r * 40 + oc] = w2[i];
    }
    for (int i = tid; i < 40;   i += NTH) sm[O_B2 + i] = b2[i];
    for (int i = tid; i < 3200; i += NTH) {
        int oc = i / 40, ic = i % 40;
        sm[O_W3T + ic * 80 + oc] = w3[i];
    }
    for (int i = tid; i < 80;   i += NTH) sm[O_B3 + i] = b3[i];
    for (int i = tid; i < 3200; i += NTH) {
        int oc = i / 80, ic = i % 80;
        sm[O_W4T + ic * 40 + oc] = w4[i];
    }
    for (int i = tid; i < 40;   i += NTH) sm[O_B4 + i] = b4[i];
    for (int i = tid; i < 2400; i += NTH) {
        int oc = i / 120, r = i % 120;           // r = ic*3 + k
        sm[O_W5T + r * 20 + oc] = w5[i];
    }
    for (int i = tid; i < 20;   i += NTH) sm[O_B5 + i] = b5[i];
    for (int i = tid; i < 20;   i += NTH) sm[O_W6 + i] = w6[i];
    if (tid == 0) sm[O_B6] = b6[0];

    // ---- stage uu window [o0-4, o0+TW+10), index-clamped ----
    for (int i = tid; i < TW + 14; i += NTH) {
        int g = o0 - 4 + i;
        g = min(max(g, 0), NTOT - 1);
        sm[O_UU + i] = uu[g];
    }
    __syncthreads();

    // ---- dif window [o0-3, o0+TW+9); zero outside [0,N) ----
    for (int i = tid; i < TW + 12; i += NTH) {
        int gi = o0 - 3 + i;
        float v = 0.f;
        if ((unsigned)gi < (unsigned)NTOT) {
            int m1 = min(gi, NTOT - 2);
            int m2 = max(gi - 1, 0);
            int base = o0 - 4;
            v = 0.5f * ((sm[O_UU + m1 + 1 - base] - sm[O_UU + m1 - base]) +
                        (sm[O_UU + m2 + 1 - base] - sm[O_UU + m2 - base]));
        }
        sm[O_DIF + i] = v;
    }
    __syncthreads();

    // ---- conv1: 1->20, k5 pad2.  A1 = X rows 0-19, base o0-1, width 264 (66 quads) ----
    for (int t = tid; t < 20 * 66; t += NTH) {
        int c = t / 66, x0 = (t % 66) * 4;
        float bias = sm[O_B1 + c];
        float c0 = bias, c1 = bias, c2 = bias, c3 = bias;
        float4 d0 = *(const float4*)&sm[O_DIF + x0];
        float4 d1 = *(const float4*)&sm[O_DIF + x0 + 4];
        float win[8] = {d0.x, d0.y, d0.z, d0.w, d1.x, d1.y, d1.z, d1.w};
        #pragma unroll
        for (int k = 0; k < 5; k++) {
            float w = sm[O_W1 + c * 5 + k];
            c0 += w * win[k]; c1 += w * win[k + 1];
            c2 += w * win[k + 2]; c3 += w * win[k + 3];
        }
        int p = o0 - 1 + x0;
        float4 r;
        r.x = (unsigned)(p + 0) < (unsigned)NTOT ? eluf(c0) : 0.f;
        r.y = (unsigned)(p + 1) < (unsigned)NTOT ? eluf(c1) : 0.f;
        r.z = (unsigned)(p + 2) < (unsigned)NTOT ? eluf(c2) : 0.f;
        r.w = (unsigned)(p + 3) < (unsigned)NTOT ? eluf(c3) : 0.f;
        *(float4*)&sm[O_X + c * ST2 + x0] = r;
    }
    __syncthreads();

    // ---- conv2: 20->40, k5 pad2.  4 oc x 4 pos.  X(A1) -> Y(A2), base o0+1, 65 quads ----
    for (int t = tid; t < 10 * 65; t += NTH) {
        int ocg = t / 65, xq = t % 65;
        int x0 = xq * 4;
        int oc0 = ocg * 4;
        float4 bv = *(const float4*)&sm[O_B2 + oc0];
        float acc0[4], acc1[4], acc2[4], acc3[4];
        #pragma unroll
        for (int p = 0; p < 4; p++) { acc0[p] = bv.x; acc1[p] = bv.y; acc2[p] = bv.z; acc3[p] = bv.w; }
        #pragma unroll 4
        for (int ic = 0; ic < 20; ic++) {
            const float* ar = &sm[O_X + ic * ST2 + x0];
            float4 v0 = *(const float4*)(ar);
            float4 v1 = *(const float4*)(ar + 4);
            float win[8] = {v0.x, v0.y, v0.z, v0.w, v1.x, v1.y, v1.z, v1.w};
            #pragma unroll
            for (int k = 0; k < 5; k++) {
                float4 w = *(const float4*)&sm[O_W2T + (ic * 5 + k) * 40 + oc0];
                #pragma unroll
                for (int p = 0; p < 4; p++) {
                    acc0[p] += w.x * win[p + k];
                    acc1[p] += w.y * win[p + k];
                    acc2[p] += w.z * win[p + k];
                    acc3[p] += w.w * win[p + k];
                }
            }
        }
        float* d0 = &sm[O_Y + oc0 * ST2 + x0];
        float4 r;
        r.x = eluf(acc0[0]); r.y = eluf(acc0[1]); r.z = eluf(acc0[2]); r.w = eluf(acc0[3]);
        *(float4*)(d0) = r;
        r.x = eluf(acc1[0]); r.y = eluf(acc1[1]); r.z = eluf(acc1[2]); r.w = eluf(acc1[3]);
        *(float4*)(d0 + ST2) = r;
        r.x = eluf(acc2[0]); r.y = eluf(acc2[1]); r.z = eluf(acc2[2]); r.w = eluf(acc2[3]);
        *(float4*)(d0 + 2 * ST2) = r;
        r.x = eluf(acc3[0]); r.y = eluf(acc3[1]); r.z = eluf(acc3[2]); r.w = eluf(acc3[3]);
        *(float4*)(d0 + 3 * ST2) = r;
    }
    __syncthreads();

    // ---- conv3: 40->80, 1x1.  8 oc x 4 pos, ic by 2.  Y(A2) -> X(A3), 65 quads ----
    for (int t = tid; t < 10 * 65; t += NTH) {
        int ocg = t / 65, xq = t % 65;
        int x0 = xq * 4;
        int oc0 = ocg * 8;
        float4 bl = *(const float4*)&sm[O_B3 + oc0];
        float4 bh = *(const float4*)&sm[O_B3 + oc0 + 4];
        float acc[8][4];
        float bb[8] = {bl.x, bl.y, bl.z, bl.w, bh.x, bh.y, bh.z, bh.w};
        #pragma unroll
        for (int c = 0; c < 8; c++)
            #pragma unroll
            for (int p = 0; p < 4; p++) acc[c][p] = bb[c];
        #pragma unroll 4
        for (int ic = 0; ic < 40; ic += 2) {
            float4 a0 = *(const float4*)&sm[O_Y + (ic + 0) * ST2 + x0];
            float4 a1 = *(const float4*)&sm[O_Y + (ic + 1) * ST2 + x0];
            float4 wl0 = *(const float4*)&sm[O_W3T + (ic + 0) * 80 + oc0];
            float4 wh0 = *(const float4*)&sm[O_W3T + (ic + 0) * 80 + oc0 + 4];
            float4 wl1 = *(const float4*)&sm[O_W3T + (ic + 1) * 80 + oc0];
            float4 wh1 = *(const float4*)&sm[O_W3T + (ic + 1) * 80 + oc0 + 4];
            float av0[4] = {a0.x, a0.y, a0.z, a0.w};
            float av1[4] = {a1.x, a1.y, a1.z, a1.w};
            float w0[8] = {wl0.x, wl0.y, wl0.z, wl0.w, wh0.x, wh0.y, wh0.z, wh0.w};
            float w1v[8] = {wl1.x, wl1.y, wl1.z, wl1.w, wh1.x, wh1.y, wh1.z, wh1.w};
            #pragma unroll
            for (int c = 0; c < 8; c++)
                #pragma unroll
                for (int p = 0; p < 4; p++)
                    acc[c][p] += w0[c] * av0[p] + w1v[c] * av1[p];
        }
        #pragma unroll
        for (int c = 0; c < 8; c++) {
            float4 r;
            r.x = eluf(acc[c][0]); r.y = eluf(acc[c][1]);
            r.z = eluf(acc[c][2]); r.w = eluf(acc[c][3]);
            *(float4*)&sm[O_X + (oc0 + c) * ST2 + x0] = r;
        }
    }
    __syncthreads();

    // ---- conv4: 80->40, 1x1.  8 oc x 2 pos, ic by 2.  X(A3) -> Y(A4); zero outside [0,N) ----
    for (int t = tid; t < 5 * 130; t += NTH) {
        int ocg = t / 130, xh = t % 130;
        int x0 = xh * 2;
        int oc0 = ocg * 8;
        float4 bl = *(const float4*)&sm[O_B4 + oc0];
        float4 bh = *(const float4*)&sm[O_B4 + oc0 + 4];
        float bb[8] = {bl.x, bl.y, bl.z, bl.w, bh.x, bh.y, bh.z, bh.w};
        float acc[8][2];
        #pragma unroll
        for (int c = 0; c < 8; c++) { acc[c][0] = bb[c]; acc[c][1] = bb[c]; }
        #pragma unroll 4
        for (int ic = 0; ic < 80; ic += 2) {
            float2 a0 = *(const float2*)&sm[O_X + (ic + 0) * ST2 + x0];
            float2 a1 = *(const float2*)&sm[O_X + (ic + 1) * ST2 + x0];
            float4 wl0 = *(const float4*)&sm[O_W4T + (ic + 0) * 40 + oc0];
            float4 wh0 = *(const float4*)&sm[O_W4T + (ic + 0) * 40 + oc0 + 4];
            float4 wl1 = *(const float4*)&sm[O_W4T + (ic + 1) * 40 + oc0];
            float4 wh1 = *(const float4*)&sm[O_W4T + (ic + 1) * 40 + oc0 + 4];
            float w0[8] = {wl0.x, wl0.y, wl0.z, wl0.w, wh0.x, wh0.y, wh0.z, wh0.w};
            float w1v[8] = {wl1.x, wl1.y, wl1.z, wl1.w, wh1.x, wh1.y, wh1.z, wh1.w};
            #pragma unroll
            for (int c = 0; c < 8; c++) {
                acc[c][0] += w0[c] * a0.x + w1v[c] * a1.x;
                acc[c][1] += w0[c] * a0.y + w1v[c] * a1.y;
            }
        }
        int p0 = o0 + 1 + x0;
        float m0 = (unsigned)(p0 + 0) < (unsigned)NTOT ? 1.f : 0.f;
        float m1 = (unsigned)(p0 + 1) < (unsigned)NTOT ? 1.f : 0.f;
        #pragma unroll
        for (int c = 0; c < 8; c++) {
            float2 r;
            r.x = m0 * eluf(acc[c][0]);
            r.y = m1 * eluf(acc[c][1]);
            *(float2*)&sm[O_Y + (oc0 + c) * ST2 + x0] = r;
        }
    }
    // zero A4 tail slots (positions 260..263, read by conv5 window at the tile edge)
    for (int t = tid; t < 40; t += NTH) {
        float4 z = {0.f, 0.f, 0.f, 0.f};
        *(float4*)&sm[O_Y + t * ST2 + (TW + 4)] = z;
    }
    __syncthreads();

    // ---- conv5: 40->20, k3 pad1.  2 oc x 4 pos.  Y(A4) -> X(A5), base o0+2, 65 quads ----
    for (int t = tid; t < 10 * 65; t += NTH) {
        int ocg = t / 65, xq = t % 65;
        int x0 = xq * 4;
        int oc0 = ocg * 2;
        float2 bv = *(const float2*)&sm[O_B5 + oc0];
        float accA[4], accB[4];
        #pragma unroll
        for (int p = 0; p < 4; p++) { accA[p] = bv.x; accB[p] = bv.y; }
        #pragma unroll 4
        for (int ic = 0; ic < 40; ic++) {
            const float* ar = &sm[O_Y + ic * ST2 + x0];
            float4 v0 = *(const float4*)(ar);
            float2 v1 = *(const float2*)(ar + 4);
            float win[6] = {v0.x, v0.y, v0.z, v0.w, v1.x, v1.y};
            #pragma unroll
            for (int k = 0; k < 3; k++) {
                float2 w = *(const float2*)&sm[O_W5T + (ic * 3 + k) * 20 + oc0];
                #pragma unroll
                for (int p = 0; p < 4; p++) {
                    accA[p] += w.x * win[p + k];
                    accB[p] += w.y * win[p + k];
                }
            }
        }
        float4 r;
        r.x = eluf(accA[0]); r.y = eluf(accA[1]); r.z = eluf(accA[2]); r.w = eluf(accA[3]);
        *(float4*)&sm[O_X + (oc0 + 0) * ST2 + x0] = r;
        r.x = eluf(accB[0]); r.y = eluf(accB[1]); r.z = eluf(accB[2]); r.w = eluf(accB[3]);
        *(float4*)&sm[O_X + (oc0 + 1) * ST2 + x0] = r;
    }
    __syncthreads();

    // ---- conv6 + sigmoid + bias: beta_mult, base o0+2, width TW+2 ----
    for (int x = tid; x < TW + 2; x += NTH) {
        float acc = sm[O_B6];
        #pragma unroll
        for (int c = 0; c < 20; c++) acc += sm[O_W6 + c] * sm[O_X + c * ST2 + x];
        sm[O_BM + x] = 1.f / (1.f + __expf(-acc)) + 0.1f;
    }
    __syncthreads();

    // ---- WENO5 flux ----
    int j = o0 + tid;
    if (tid < TW && j < NOUT) {
        const float* U = &sm[O_UU + tid + 5];   // uu[j+1 .. j+6]
        float v0 = U[0], v1 = U[1], v2 = U[2], v3 = U[3], v4 = U[4], v5 = U[5];
        float m0 = sm[O_BM + tid];
        float m1 = sm[O_BM + tid + 1];
        float m2 = sm[O_BM + tid + 2];
        float e = e_p[0];
        float fluxp = weno_side(v1, v2, v3, v4, v5, m0, m1, m2, e);
        float fluxn = weno_side(v0, v1, v2, v3, v4, m0, m1, m2, e);
        out[j] = fluxp - fluxn;
    }
}

extern "C" void kernel_launch(void* const* d_in, const int* in_sizes, int n_in,
                              void* d_out, int out_size) {
    const float* uu = (const float*)d_in[0];
    const float* e  = (const float*)d_in[1];
    const float* w1 = (const float*)d_in[2];
    const float* b1 = (const float*)d_in[3];
    const float* w2 = (const float*)d_in[4];
    const float* b2 = (const float*)d_in[5];
    const float* w3 = (const float*)d_in[6];
    const float* b3 = (const float*)d_in[7];
    const float* w4 = (const float*)d_in[8];
    const float* b4 = (const float*)d_in[9];
    const float* w5 = (const float*)d_in[10];
    const float* b5 = (const float*)d_in[11];
    const float* w6 = (const float*)d_in[12];
    const float* b6 = (const float*)d_in[13];
    float* out = (float*)d_out;

    cudaFuncSetAttribute(weno_fused, cudaFuncAttributeMaxDynamicSharedMemorySize, SMEM_BYTES);
    int grid = (NOUT + TW - 1) / TW;
    weno_fused<<<grid, NTH, SMEM_BYTES>>>(uu, e, w1, b1, w2, b2, w3, b3, w4, b4,
                                          w5, b5, w6, b6, out);
}

// round 6
// speedup vs baseline: 7.5900x; 1.1049x over previous
#include <cuda_runtime.h>
#include <math.h>

#define NTH 640
#define TW  256           // outputs per block

constexpr int NTOT = 2097152;
constexpr int NOUT = NTOT - 6;
constexpr int ST2  = TW + 8;   // 264: activation row stride (floats), 16B-aligned

// ---- shared-memory weight offsets (floats); transposed oc-contiguous layouts ----
constexpr int O_W1  = 0;                 // 100   w1[oc][k] (as-is)
constexpr int O_B1  = 100;               // 20
constexpr int O_W2T = 120;               // 4000  T2[(ic*5+k)*40 + oc]
constexpr int O_B2  = 4120;              // 40
constexpr int O_W3T = 4160;              // 3200  T3[ic*80 + oc]
constexpr int O_B3  = 7360;              // 80
constexpr int O_W4T = 7440;              // 3200  T4[ic*40 + oc]
constexpr int O_B4  = 10640;             // 40
constexpr int O_W5T = 10680;             // 2400  T5[(ic*3+k)*20 + oc]
constexpr int O_B5  = 13080;             // 20
constexpr int O_W6  = 13100;             // 20
constexpr int O_B6  = 13120;             // 1 (+3 pad)
// ---- activation area ----
constexpr int O_UU  = 13124;             // 272 alloc (need TW+14)
constexpr int O_DIF = O_UU + 272;        // 272 alloc (need TW+12)
constexpr int O_BM  = O_DIF + 272;       // 264 alloc (need TW+2)
constexpr int O_Y   = O_BM + 264;        // 40*ST2  (A2, A4)
constexpr int O_X   = O_Y + 40 * ST2;    // 80*ST2  (A1 rows 0-19, A3 all, A5 rows 0-19)
constexpr int SMEM_FLOATS = O_X + 80 * ST2;
constexpr int SMEM_BYTES  = SMEM_FLOATS * 4;   // ~178 KB

typedef unsigned long long u64;

__device__ __forceinline__ u64 dup2(float x) {
    u64 r;
    asm("mov.b64 %0, {%1, %1};" : "=l"(r) : "f"(x));
    return r;
}
__device__ __forceinline__ u64 pack2(float lo, float hi) {
    u64 r;
    asm("mov.b64 %0, {%1, %2};" : "=l"(r) : "f"(lo), "f"(hi));
    return r;
}
__device__ __forceinline__ void unpack2(u64 v, float& lo, float& hi) {
    asm("mov.b64 {%0, %1}, %2;" : "=f"(lo), "=f"(hi) : "l"(v));
}
__device__ __forceinline__ void fma2(u64& acc, u64 w, u64 a) {
    asm("fma.rn.f32x2 %0, %1, %2, %0;" : "+l"(acc) : "l"(w), "l"(a));
}

__device__ __forceinline__ float eluf(float x) {
    return x > 0.f ? x : (__expf(x) - 1.f);
}

__device__ __forceinline__ float weno_side(float u0, float u1, float u2, float u3, float u4,
                                           float m0, float m1, float m2, float e) {
    const float c16 = 1.f / 6.f;
    float f0 = (11.f * u2 - 7.f * u3 + 2.f * u4) * c16;
    float f1 = (2.f * u1 + 5.f * u2 - u3) * c16;
    float f2 = (-u0 + 5.f * u1 + 2.f * u2) * c16;
    float t, b0, b1, b2;
    t = u2 - 2.f * u3 + u4;          b0 = (13.f / 12.f) * t * t;
    t = 3.f * u2 - 4.f * u3 + u4;    b0 += 0.25f * t * t;
    t = u1 - 2.f * u2 + u3;          b1 = (13.f / 12.f) * t * t;
    t = u1 - u3;                     b1 += 0.25f * t * t;
    t = u0 - 2.f * u1 + u2;          b2 = (13.f / 12.f) * t * t;
    t = u0 - 4.f * u1 + 3.f * u2;    b2 += 0.25f * t * t;
    b0 *= m0; b1 *= m1; b2 *= m2;
    float brs = (b2 - b0) * (b2 - b0);
    float q0 = (e + b0) * (e + b0);
    float q1 = (e + b1) * (e + b1);
    float q2 = (e + b2) * (e + b2);
    float o0 = 0.1f / q0 * (brs + q0);
    float o1 = 0.6f / q1 * (brs + q1);
    float o2 = 0.3f / q2 * (brs + q2);
    float s = o0 + o1 + o2;
    return (o0 * f0 + o1 * f1 + o2 * f2) / s;
}

__global__ __launch_bounds__(NTH, 1)
void weno_fused(const float* __restrict__ uu, const float* __restrict__ e_p,
                const float* __restrict__ w1, const float* __restrict__ b1,
                const float* __restrict__ w2, const float* __restrict__ b2,
                const float* __restrict__ w3, const float* __restrict__ b3,
                const float* __restrict__ w4, const float* __restrict__ b4,
                const float* __restrict__ w5, const float* __restrict__ b5,
                const float* __restrict__ w6, const float* __restrict__ b6,
                float* __restrict__ out) {
    extern __shared__ float sm[];
    const int tid = threadIdx.x;
    const int o0 = blockIdx.x * TW;

    // ---- stage weights (transposed to oc-contiguous) ----
    for (int i = tid; i < 100;  i += NTH) sm[O_W1 + i] = w1[i];
    for (int i = tid; i < 20;   i += NTH) sm[O_B1 + i] = b1[i];
    for (int i = tid; i < 4000; i += NTH) {
        int oc = i / 100, r = i % 100;           // r = ic*5 + k
        sm[O_W2T + r * 40 + oc] = w2[i];
    }
    for (int i = tid; i < 40;   i += NTH) sm[O_B2 + i] = b2[i];
    for (int i = tid; i < 3200; i += NTH) {
        int oc = i / 40, ic = i % 40;
        sm[O_W3T + ic * 80 + oc] = w3[i];
    }
    for (int i = tid; i < 80;   i += NTH) sm[O_B3 + i] = b3[i];
    for (int i = tid; i < 3200; i += NTH) {
        int oc = i / 80, ic = i % 80;
        sm[O_W4T + ic * 40 + oc] = w4[i];
    }
    for (int i = tid; i < 40;   i += NTH) sm[O_B4 + i] = b4[i];
    for (int i = tid; i < 2400; i += NTH) {
        int oc = i / 120, r = i % 120;           // r = ic*3 + k
        sm[O_W5T + r * 20 + oc] = w5[i];
    }
    for (int i = tid; i < 20;   i += NTH) sm[O_B5 + i] = b5[i];
    for (int i = tid; i < 20;   i += NTH) sm[O_W6 + i] = w6[i];
    if (tid == 0) sm[O_B6] = b6[0];

    // ---- stage uu window [o0-4, o0+TW+10), index-clamped ----
    for (int i = tid; i < TW + 14; i += NTH) {
        int g = o0 - 4 + i;
        g = min(max(g, 0), NTOT - 1);
        sm[O_UU + i] = uu[g];
    }
    __syncthreads();

    // ---- dif window [o0-3, o0+TW+9); zero outside [0,N) ----
    for (int i = tid; i < TW + 12; i += NTH) {
        int gi = o0 - 3 + i;
        float v = 0.f;
        if ((unsigned)gi < (unsigned)NTOT) {
            int m1 = min(gi, NTOT - 2);
            int m2 = max(gi - 1, 0);
            int base = o0 - 4;
            v = 0.5f * ((sm[O_UU + m1 + 1 - base] - sm[O_UU + m1 - base]) +
                        (sm[O_UU + m2 + 1 - base] - sm[O_UU + m2 - base]));
        }
        sm[O_DIF + i] = v;
    }
    __syncthreads();

    // ---- conv1: 1->20, k5 pad2.  A1 = X rows 0-19, base o0-1, width 264 (66 quads) ----
    for (int t = tid; t < 20 * 66; t += NTH) {
        int c = t / 66, x0 = (t % 66) * 4;
        float bias = sm[O_B1 + c];
        float c0 = bias, c1 = bias, c2 = bias, c3 = bias;
        float4 d0 = *(const float4*)&sm[O_DIF + x0];
        float4 d1 = *(const float4*)&sm[O_DIF + x0 + 4];
        float win[8] = {d0.x, d0.y, d0.z, d0.w, d1.x, d1.y, d1.z, d1.w};
        #pragma unroll
        for (int k = 0; k < 5; k++) {
            float w = sm[O_W1 + c * 5 + k];
            c0 += w * win[k]; c1 += w * win[k + 1];
            c2 += w * win[k + 2]; c3 += w * win[k + 3];
        }
        int p = o0 - 1 + x0;
        float4 r;
        r.x = (unsigned)(p + 0) < (unsigned)NTOT ? eluf(c0) : 0.f;
        r.y = (unsigned)(p + 1) < (unsigned)NTOT ? eluf(c1) : 0.f;
        r.z = (unsigned)(p + 2) < (unsigned)NTOT ? eluf(c2) : 0.f;
        r.w = (unsigned)(p + 3) < (unsigned)NTOT ? eluf(c3) : 0.f;
        *(float4*)&sm[O_X + c * ST2 + x0] = r;
    }
    __syncthreads();

    // ---- conv2: 20->40, k5 pad2.  f32x2 over oc-pairs: 4 oc x 4 pos.  X(A1)->Y(A2) ----
    for (int t = tid; t < 10 * 65; t += NTH) {
        int ocg = t / 65, xq = t % 65;
        int x0 = xq * 4;
        int oc0 = ocg * 4;
        u64 acc0[4], acc1[4];   // pair0=(oc0,oc0+1), pair1=(oc0+2,oc0+3)
        {
            float4 bv = *(const float4*)&sm[O_B2 + oc0];
            u64 b01 = pack2(bv.x, bv.y), b23 = pack2(bv.z, bv.w);
            #pragma unroll
            for (int p = 0; p < 4; p++) { acc0[p] = b01; acc1[p] = b23; }
        }
        #pragma unroll 4
        for (int ic = 0; ic < 20; ic++) {
            const float* ar = &sm[O_X + ic * ST2 + x0];
            float4 v0 = *(const float4*)(ar);
            float4 v1 = *(const float4*)(ar + 4);
            u64 dwin[8] = {dup2(v0.x), dup2(v0.y), dup2(v0.z), dup2(v0.w),
                           dup2(v1.x), dup2(v1.y), dup2(v1.z), dup2(v1.w)};
            #pragma unroll
            for (int k = 0; k < 5; k++) {
                ulonglong2 wv = *(const ulonglong2*)&sm[O_W2T + (ic * 5 + k) * 40 + oc0];
                #pragma unroll
                for (int p = 0; p < 4; p++) {
                    fma2(acc0[p], wv.x, dwin[p + k]);
                    fma2(acc1[p], wv.y, dwin[p + k]);
                }
            }
        }
        float r0[4], r1[4], r2[4], r3[4];
        #pragma unroll
        for (int p = 0; p < 4; p++) {
            float lo, hi;
            unpack2(acc0[p], lo, hi); r0[p] = eluf(lo); r1[p] = eluf(hi);
            unpack2(acc1[p], lo, hi); r2[p] = eluf(lo); r3[p] = eluf(hi);
        }
        float* d0 = &sm[O_Y + oc0 * ST2 + x0];
        *(float4*)(d0)           = make_float4(r0[0], r0[1], r0[2], r0[3]);
        *(float4*)(d0 + ST2)     = make_float4(r1[0], r1[1], r1[2], r1[3]);
        *(float4*)(d0 + 2 * ST2) = make_float4(r2[0], r2[1], r2[2], r2[3]);
        *(float4*)(d0 + 3 * ST2) = make_float4(r3[0], r3[1], r3[2], r3[3]);
    }
    __syncthreads();

    // ---- conv3: 40->80, 1x1.  f32x2 over oc-pairs: 8 oc x 4 pos.  Y(A2)->X(A3) ----
    for (int t = tid; t < 10 * 65; t += NTH) {
        int ocg = t / 65, xq = t % 65;
        int x0 = xq * 4;
        int oc0 = ocg * 8;
        u64 acc[4][4];   // [oc pair][pos]
        {
            float4 bl = *(const float4*)&sm[O_B3 + oc0];
            float4 bh = *(const float4*)&sm[O_B3 + oc0 + 4];
            u64 bp[4] = {pack2(bl.x, bl.y), pack2(bl.z, bl.w),
                         pack2(bh.x, bh.y), pack2(bh.z, bh.w)};
            #pragma unroll
            for (int c = 0; c < 4; c++)
                #pragma unroll
                for (int p = 0; p < 4; p++) acc[c][p] = bp[c];
        }
        #pragma unroll 4
        for (int ic = 0; ic < 40; ic++) {
            ulonglong2 wl = *(const ulonglong2*)&sm[O_W3T + ic * 80 + oc0];
            ulonglong2 wh = *(const ulonglong2*)&sm[O_W3T + ic * 80 + oc0 + 4];
            float4 a = *(const float4*)&sm[O_Y + ic * ST2 + x0];
            u64 da[4] = {dup2(a.x), dup2(a.y), dup2(a.z), dup2(a.w)};
            #pragma unroll
            for (int p = 0; p < 4; p++) {
                fma2(acc[0][p], wl.x, da[p]);
                fma2(acc[1][p], wl.y, da[p]);
                fma2(acc[2][p], wh.x, da[p]);
                fma2(acc[3][p], wh.y, da[p]);
            }
        }
        #pragma unroll
        for (int c = 0; c < 4; c++) {
            float lo0, hi0, lo1, hi1, lo2, hi2, lo3, hi3;
            unpack2(acc[c][0], lo0, hi0); unpack2(acc[c][1], lo1, hi1);
            unpack2(acc[c][2], lo2, hi2); unpack2(acc[c][3], lo3, hi3);
            *(float4*)&sm[O_X + (oc0 + 2 * c) * ST2 + x0] =
                make_float4(eluf(lo0), eluf(lo1), eluf(lo2), eluf(lo3));
            *(float4*)&sm[O_X + (oc0 + 2 * c + 1) * ST2 + x0] =
                make_float4(eluf(hi0), eluf(hi1), eluf(hi2), eluf(hi3));
        }
    }
    __syncthreads();

    // ---- conv4: 80->40, 1x1.  f32x2 over oc-pairs: 8 oc x 2 pos.  X(A3)->Y(A4) ----
    for (int t = tid; t < 5 * 130; t += NTH) {
        int ocg = t / 130, xh = t % 130;
        int x0 = xh * 2;
        int oc0 = ocg * 8;
        u64 acc[4][2];
        {
            float4 bl = *(const float4*)&sm[O_B4 + oc0];
            float4 bh = *(const float4*)&sm[O_B4 + oc0 + 4];
            u64 bp[4] = {pack2(bl.x, bl.y), pack2(bl.z, bl.w),
                         pack2(bh.x, bh.y), pack2(bh.z, bh.w)};
            #pragma unroll
            for (int c = 0; c < 4; c++) { acc[c][0] = bp[c]; acc[c][1] = bp[c]; }
        }
        #pragma unroll 4
        for (int ic = 0; ic < 80; ic++) {
            ulonglong2 wl = *(const ulonglong2*)&sm[O_W4T + ic * 40 + oc0];
            ulonglong2 wh = *(const ulonglong2*)&sm[O_W4T + ic * 40 + oc0 + 4];
            float2 a = *(const float2*)&sm[O_X + ic * ST2 + x0];
            u64 da0 = dup2(a.x), da1 = dup2(a.y);
            fma2(acc[0][0], wl.x, da0); fma2(acc[0][1], wl.x, da1);
            fma2(acc[1][0], wl.y, da0); fma2(acc[1][1], wl.y, da1);
            fma2(acc[2][0], wh.x, da0); fma2(acc[2][1], wh.x, da1);
            fma2(acc[3][0], wh.y, da0); fma2(acc[3][1], wh.y, da1);
        }
        int p0 = o0 + 1 + x0;
        float m0 = (unsigned)(p0 + 0) < (unsigned)NTOT ? 1.f : 0.f;
        float m1 = (unsigned)(p0 + 1) < (unsigned)NTOT ? 1.f : 0.f;
        #pragma unroll
        for (int c = 0; c < 4; c++) {
            float lo0, hi0, lo1, hi1;
            unpack2(acc[c][0], lo0, hi0);
            unpack2(acc[c][1], lo1, hi1);
            *(float2*)&sm[O_Y + (oc0 + 2 * c) * ST2 + x0] =
                make_float2(m0 * eluf(lo0), m1 * eluf(lo1));
            *(float2*)&sm[O_Y + (oc0 + 2 * c + 1) * ST2 + x0] =
                make_float2(m0 * eluf(hi0), m1 * eluf(hi1));
        }
    }
    // zero A4 tail slots (positions 260..263, read by conv5 window at the tile edge)
    for (int t = tid; t < 40; t += NTH) {
        float4 z = {0.f, 0.f, 0.f, 0.f};
        *(float4*)&sm[O_Y + t * ST2 + (TW + 4)] = z;
    }
    __syncthreads();

    // ---- conv5: 40->20, k3 pad1.  f32x2 over oc-pair: 2 oc x 4 pos.  Y(A4)->X(A5) ----
    for (int t = tid; t < 10 * 65; t += NTH) {
        int ocg = t / 65, xq = t % 65;
        int x0 = xq * 4;
        int oc0 = ocg * 2;
        u64 acc[4];
        {
            float2 bv = *(const float2*)&sm[O_B5 + oc0];
            u64 b = pack2(bv.x, bv.y);
            #pragma unroll
            for (int p = 0; p < 4; p++) acc[p] = b;
        }
        #pragma unroll 4
        for (int ic = 0; ic < 40; ic++) {
            const float* ar = &sm[O_Y + ic * ST2 + x0];
            float4 v0 = *(const float4*)(ar);
            float2 v1 = *(const float2*)(ar + 4);
            u64 dwin[6] = {dup2(v0.x), dup2(v0.y), dup2(v0.z), dup2(v0.w),
                           dup2(v1.x), dup2(v1.y)};
            #pragma unroll
            for (int k = 0; k < 3; k++) {
                u64 w = *(const u64*)&sm[O_W5T + (ic * 3 + k) * 20 + oc0];
                #pragma unroll
                for (int p = 0; p < 4; p++) fma2(acc[p], w, dwin[p + k]);
            }
        }
        float loA[4], hiA[4];
        #pragma unroll
        for (int p = 0; p < 4; p++) unpack2(acc[p], loA[p], hiA[p]);
        *(float4*)&sm[O_X + (oc0 + 0) * ST2 + x0] =
            make_float4(eluf(loA[0]), eluf(loA[1]), eluf(loA[2]), eluf(loA[3]));
        *(float4*)&sm[O_X + (oc0 + 1) * ST2 + x0] =
            make_float4(eluf(hiA[0]), eluf(hiA[1]), eluf(hiA[2]), eluf(hiA[3]));
    }
    __syncthreads();

    // ---- conv6 + sigmoid + bias: beta_mult, base o0+2, width TW+2 ----
    for (int x = tid; x < TW + 2; x += NTH) {
        float acc = sm[O_B6];
        #pragma unroll
        for (int c = 0; c < 20; c++) acc += sm[O_W6 + c] * sm[O_X + c * ST2 + x];
        sm[O_BM + x] = 1.f / (1.f + __expf(-acc)) + 0.1f;
    }
    __syncthreads();

    // ---- WENO5 flux ----
    int j = o0 + tid;
    if (tid < TW && j < NOUT) {
        const float* U = &sm[O_UU + tid + 5];   // uu[j+1 .. j+6]
        float v0 = U[0], v1 = U[1], v2 = U[2], v3 = U[3], v4 = U[4], v5 = U[5];
        float m0 = sm[O_BM + tid];
        float m1 = sm[O_BM + tid + 1];
        float m2 = sm[O_BM + tid + 2];
        float e = e_p[0];
        float fluxp = weno_side(v1, v2, v3, v4, v5, m0, m1, m2, e);
        float fluxn = weno_side(v0, v1, v2, v3, v4, m0, m1, m2, e);
        out[j] = fluxp - fluxn;
    }
}

extern "C" void kernel_launch(void* const* d_in, const int* in_sizes, int n_in,
                              void* d_out, int out_size) {
    const float* uu = (const float*)d_in[0];
    const float* e  = (const float*)d_in[1];
    const float* w1 = (const float*)d_in[2];
    const float* b1 = (const float*)d_in[3];
    const float* w2 = (const float*)d_in[4];
    const float* b2 = (const float*)d_in[5];
    const float* w3 = (const float*)d_in[6];
    const float* b3 = (const float*)d_in[7];
    const float* w4 = (const float*)d_in[8];
    const float* b4 = (const float*)d_in[9];
    const float* w5 = (const float*)d_in[10];
    const float* b5 = (const float*)d_in[11];
    const float* w6 = (const float*)d_in[12];
    const float* b6 = (const float*)d_in[13];
    float* out = (float*)d_out;

    cudaFuncSetAttribute(weno_fused, cudaFuncAttributeMaxDynamicSharedMemorySize, SMEM_BYTES);
    int grid = (NOUT + TW - 1) / TW;
    weno_fused<<<grid, NTH, SMEM_BYTES>>>(uu, e, w1, b1, w2, b2, w3, b3, w4, b4,
                                          w5, b5, w6, b6, out);
}

// round 7
// speedup vs baseline: 7.8161x; 1.0298x over previous
#include <cuda_runtime.h>
#include <math.h>

#define NTH 384
#define TW  256           // outputs per block

constexpr int NTOT = 2097152;
constexpr int NOUT = NTOT - 6;
constexpr int ST2  = 272;  // activation row stride (floats), 16B-aligned, conflict-safe

// ---- shared-memory weight offsets (floats); transposed oc-contiguous layouts ----
constexpr int O_W1  = 0;                 // 100   w1[oc][k] (as-is)
constexpr int O_B1  = 100;               // 20
constexpr int O_W2T = 120;               // 4000  T2[(ic*5+k)*40 + oc]
constexpr int O_B2  = 4120;              // 40
constexpr int O_W3T = 4160;              // 3200  T3[ic*80 + oc]
constexpr int O_B3  = 7360;              // 80
constexpr int O_W4T = 7440;              // 3200  T4[ic*40 + oc]
constexpr int O_B4  = 10640;             // 40
constexpr int O_W5T = 10680;             // 2400  T5[(ic*3+k)*20 + oc]
constexpr int O_B5  = 13080;             // 20
constexpr int O_W6  = 13100;             // 20
constexpr int O_B6  = 13120;             // 1 (+3 pad)
// ---- activation area ----
constexpr int O_UU  = 13124;             // alloc 272 (need TW+14=270)
constexpr int O_DIF = O_UU + 272;        // alloc 272 (need TW+12=268)
constexpr int O_BM  = O_DIF + 272;       // alloc 272 (need TW+2=258)
constexpr int O_Y   = O_BM + 272;        // 40*ST2  (A2, A4)
constexpr int O_X   = O_Y + 40 * ST2;    // 80*ST2  (A1 rows 0-19, A3 all, A5 rows 0-19)
constexpr int SMEM_FLOATS = O_X + 80 * ST2;
constexpr int SMEM_BYTES  = SMEM_FLOATS * 4;   // ~186 KB

typedef unsigned long long u64;

__device__ __forceinline__ u64 dup2(float x) {
    u64 r;
    asm("mov.b64 %0, {%1, %1};" : "=l"(r) : "f"(x));
    return r;
}
__device__ __forceinline__ u64 pack2(float lo, float hi) {
    u64 r;
    asm("mov.b64 %0, {%1, %2};" : "=l"(r) : "f"(lo), "f"(hi));
    return r;
}
__device__ __forceinline__ void unpack2(u64 v, float& lo, float& hi) {
    asm("mov.b64 {%0, %1}, %2;" : "=f"(lo), "=f"(hi) : "l"(v));
}
__device__ __forceinline__ void fma2(u64& acc, u64 w, u64 a) {
    asm("fma.rn.f32x2 %0, %1, %2, %0;" : "+l"(acc) : "l"(w), "l"(a));
}

__device__ __forceinline__ float eluf(float x) {
    return x > 0.f ? x : (__expf(x) - 1.f);
}

__device__ __forceinline__ float weno_side(float u0, float u1, float u2, float u3, float u4,
                                           float m0, float m1, float m2, float e) {
    const float c16 = 1.f / 6.f;
    float f0 = (11.f * u2 - 7.f * u3 + 2.f * u4) * c16;
    float f1 = (2.f * u1 + 5.f * u2 - u3) * c16;
    float f2 = (-u0 + 5.f * u1 + 2.f * u2) * c16;
    float t, b0, b1, b2;
    t = u2 - 2.f * u3 + u4;          b0 = (13.f / 12.f) * t * t;
    t = 3.f * u2 - 4.f * u3 + u4;    b0 += 0.25f * t * t;
    t = u1 - 2.f * u2 + u3;          b1 = (13.f / 12.f) * t * t;
    t = u1 - u3;                     b1 += 0.25f * t * t;
    t = u0 - 2.f * u1 + u2;          b2 = (13.f / 12.f) * t * t;
    t = u0 - 4.f * u1 + 3.f * u2;    b2 += 0.25f * t * t;
    b0 *= m0; b1 *= m1; b2 *= m2;
    float brs = (b2 - b0) * (b2 - b0);
    float q0 = (e + b0) * (e + b0);
    float q1 = (e + b1) * (e + b1);
    float q2 = (e + b2) * (e + b2);
    float o0 = 0.1f / q0 * (brs + q0);
    float o1 = 0.6f / q1 * (brs + q1);
    float o2 = 0.3f / q2 * (brs + q2);
    float s = o0 + o1 + o2;
    return (o0 * f0 + o1 * f1 + o2 * f2) / s;
}

__global__ __launch_bounds__(NTH, 1)
void weno_fused(const float* __restrict__ uu, const float* __restrict__ e_p,
                const float* __restrict__ w1, const float* __restrict__ b1,
                const float* __restrict__ w2, const float* __restrict__ b2,
                const float* __restrict__ w3, const float* __restrict__ b3,
                const float* __restrict__ w4, const float* __restrict__ b4,
                const float* __restrict__ w5, const float* __restrict__ b5,
                const float* __restrict__ w6, const float* __restrict__ b6,
                float* __restrict__ out) {
    extern __shared__ float sm[];
    const int tid = threadIdx.x;
    const int o0 = blockIdx.x * TW;

    // ---- stage weights (transposed to oc-contiguous) ----
    for (int i = tid; i < 100;  i += NTH) sm[O_W1 + i] = w1[i];
    for (int i = tid; i < 20;   i += NTH) sm[O_B1 + i] = b1[i];
    for (int i = tid; i < 4000; i += NTH) {
        int oc = i / 100, r = i % 100;           // r = ic*5 + k
        sm[O_W2T + r * 40 + oc] = w2[i];
    }
    for (int i = tid; i < 40;   i += NTH) sm[O_B2 + i] = b2[i];
    for (int i = tid; i < 3200; i += NTH) {
        int oc = i / 40, ic = i % 40;
        sm[O_W3T + ic * 80 + oc] = w3[i];
    }
    for (int i = tid; i < 80;   i += NTH) sm[O_B3 + i] = b3[i];
    for (int i = tid; i < 3200; i += NTH) {
        int oc = i / 80, ic = i % 80;
        sm[O_W4T + ic * 40 + oc] = w4[i];
    }
    for (int i = tid; i < 40;   i += NTH) sm[O_B4 + i] = b4[i];
    for (int i = tid; i < 2400; i += NTH) {
        int oc = i / 120, r = i % 120;           // r = ic*3 + k
        sm[O_W5T + r * 20 + oc] = w5[i];
    }
    for (int i = tid; i < 20;   i += NTH) sm[O_B5 + i] = b5[i];
    for (int i = tid; i < 20;   i += NTH) sm[O_W6 + i] = w6[i];
    if (tid == 0) sm[O_B6] = b6[0];

    // ---- stage uu window [o0-4, o0+TW+10), index-clamped ----
    for (int i = tid; i < TW + 14; i += NTH) {
        int g = o0 - 4 + i;
        g = min(max(g, 0), NTOT - 1);
        sm[O_UU + i] = uu[g];
    }
    __syncthreads();

    // ---- dif window [o0-3, o0+TW+9); zero outside [0,N) ----
    for (int i = tid; i < TW + 12; i += NTH) {
        int gi = o0 - 3 + i;
        float v = 0.f;
        if ((unsigned)gi < (unsigned)NTOT) {
            int m1 = min(gi, NTOT - 2);
            int m2 = max(gi - 1, 0);
            int base = o0 - 4;
            v = 0.5f * ((sm[O_UU + m1 + 1 - base] - sm[O_UU + m1 - base]) +
                        (sm[O_UU + m2 + 1 - base] - sm[O_UU + m2 - base]));
        }
        sm[O_DIF + i] = v;
    }
    __syncthreads();

    // ---- conv1: 1->20, k5 pad2.  P=8.  A1 = X rows 0-19, base o0-1, width 264 (33 chunks) ----
    for (int t = tid; t < 20 * 33; t += NTH) {
        int c = t / 33, x0 = (t % 33) * 8;
        float bias = sm[O_B1 + c];
        float acc[8];
        #pragma unroll
        for (int p = 0; p < 8; p++) acc[p] = bias;
        float4 d0 = *(const float4*)&sm[O_DIF + x0];
        float4 d1 = *(const float4*)&sm[O_DIF + x0 + 4];
        float4 d2 = *(const float4*)&sm[O_DIF + x0 + 8];
        float win[12] = {d0.x, d0.y, d0.z, d0.w, d1.x, d1.y, d1.z, d1.w,
                         d2.x, d2.y, d2.z, d2.w};
        #pragma unroll
        for (int k = 0; k < 5; k++) {
            float w = sm[O_W1 + c * 5 + k];
            #pragma unroll
            for (int p = 0; p < 8; p++) acc[p] += w * win[p + k];
        }
        int pg = o0 - 1 + x0;
        float r[8];
        #pragma unroll
        for (int p = 0; p < 8; p++)
            r[p] = (unsigned)(pg + p) < (unsigned)NTOT ? eluf(acc[p]) : 0.f;
        float* d = &sm[O_X + c * ST2 + x0];
        *(float4*)(d)     = make_float4(r[0], r[1], r[2], r[3]);
        *(float4*)(d + 4) = make_float4(r[4], r[5], r[6], r[7]);
    }
    __syncthreads();

    // ---- conv2: 20->40, k5 pad2.  oc-paired f32x2, C=4, P=8.  X(A1)->Y(A2), base o0+1 ----
    for (int t = tid; t < 10 * 33; t += NTH) {
        int ocg = t / 33, x0 = (t % 33) * 8;
        int oc0 = ocg * 4;
        u64 acc0[8], acc1[8];
        {
            float4 bv = *(const float4*)&sm[O_B2 + oc0];
            u64 b01 = pack2(bv.x, bv.y), b23 = pack2(bv.z, bv.w);
            #pragma unroll
            for (int p = 0; p < 8; p++) { acc0[p] = b01; acc1[p] = b23; }
        }
        #pragma unroll 4
        for (int ic = 0; ic < 20; ic++) {
            const float* ar = &sm[O_X + ic * ST2 + x0];
            float4 v0 = *(const float4*)(ar);
            float4 v1 = *(const float4*)(ar + 4);
            float4 v2 = *(const float4*)(ar + 8);
            u64 dwin[12] = {dup2(v0.x), dup2(v0.y), dup2(v0.z), dup2(v0.w),
                            dup2(v1.x), dup2(v1.y), dup2(v1.z), dup2(v1.w),
                            dup2(v2.x), dup2(v2.y), dup2(v2.z), dup2(v2.w)};
            #pragma unroll
            for (int k = 0; k < 5; k++) {
                ulonglong2 wv = *(const ulonglong2*)&sm[O_W2T + (ic * 5 + k) * 40 + oc0];
                #pragma unroll
                for (int p = 0; p < 8; p++) {
                    fma2(acc0[p], wv.x, dwin[p + k]);
                    fma2(acc1[p], wv.y, dwin[p + k]);
                }
            }
        }
        float rA[8], rB[8], rC[8], rD[8];
        #pragma unroll
        for (int p = 0; p < 8; p++) {
            float lo, hi;
            unpack2(acc0[p], lo, hi); rA[p] = eluf(lo); rB[p] = eluf(hi);
            unpack2(acc1[p], lo, hi); rC[p] = eluf(lo); rD[p] = eluf(hi);
        }
        float* d0 = &sm[O_Y + oc0 * ST2 + x0];
        *(float4*)(d0)               = make_float4(rA[0], rA[1], rA[2], rA[3]);
        *(float4*)(d0 + 4)           = make_float4(rA[4], rA[5], rA[6], rA[7]);
        *(float4*)(d0 + ST2)         = make_float4(rB[0], rB[1], rB[2], rB[3]);
        *(float4*)(d0 + ST2 + 4)     = make_float4(rB[4], rB[5], rB[6], rB[7]);
        *(float4*)(d0 + 2 * ST2)     = make_float4(rC[0], rC[1], rC[2], rC[3]);
        *(float4*)(d0 + 2 * ST2 + 4) = make_float4(rC[4], rC[5], rC[6], rC[7]);
        *(float4*)(d0 + 3 * ST2)     = make_float4(rD[0], rD[1], rD[2], rD[3]);
        *(float4*)(d0 + 3 * ST2 + 4) = make_float4(rD[4], rD[5], rD[6], rD[7]);
    }
    __syncthreads();

    // ---- conv3: 40->80, 1x1.  pos-packed f32x2, C=8, P=8.  Y(A2)->X(A3) ----
    for (int t = tid; t < 10 * 33; t += NTH) {
        int ocg = t / 33, x0 = (t % 33) * 8;
        int oc0 = ocg * 8;
        u64 acc[8][4];
        {
            float4 bl = *(const float4*)&sm[O_B3 + oc0];
            float4 bh = *(const float4*)&sm[O_B3 + oc0 + 4];
            float bb[8] = {bl.x, bl.y, bl.z, bl.w, bh.x, bh.y, bh.z, bh.w};
            #pragma unroll
            for (int c = 0; c < 8; c++) {
                u64 bd = dup2(bb[c]);
                #pragma unroll
                for (int j = 0; j < 4; j++) acc[c][j] = bd;
            }
        }
        #pragma unroll 4
        for (int ic = 0; ic < 40; ic++) {
            ulonglong2 a01 = *(const ulonglong2*)&sm[O_Y + ic * ST2 + x0];
            ulonglong2 a23 = *(const ulonglong2*)&sm[O_Y + ic * ST2 + x0 + 4];
            u64 av[4] = {a01.x, a01.y, a23.x, a23.y};
            float4 w0 = *(const float4*)&sm[O_W3T + ic * 80 + oc0];
            float4 w1v = *(const float4*)&sm[O_W3T + ic * 80 + oc0 + 4];
            u64 dw[8] = {dup2(w0.x), dup2(w0.y), dup2(w0.z), dup2(w0.w),
                         dup2(w1v.x), dup2(w1v.y), dup2(w1v.z), dup2(w1v.w)};
            #pragma unroll
            for (int c = 0; c < 8; c++)
                #pragma unroll
                for (int j = 0; j < 4; j++) fma2(acc[c][j], dw[c], av[j]);
        }
        #pragma unroll
        for (int c = 0; c < 8; c++) {
            float f[8];
            #pragma unroll
            for (int j = 0; j < 4; j++) unpack2(acc[c][j], f[2 * j], f[2 * j + 1]);
            float* d = &sm[O_X + (oc0 + c) * ST2 + x0];
            *(float4*)(d)     = make_float4(eluf(f[0]), eluf(f[1]), eluf(f[2]), eluf(f[3]));
            *(float4*)(d + 4) = make_float4(eluf(f[4]), eluf(f[5]), eluf(f[6]), eluf(f[7]));
        }
    }
    __syncthreads();

    // ---- conv4: 80->40, 1x1.  pos-packed f32x2, C=8, P=4.  X(A3)->Y(A4); zero outside [0,N) ----
    for (int t = tid; t < 5 * 65; t += NTH) {
        int ocg = t / 65, x0 = (t % 65) * 4;
        int oc0 = ocg * 8;
        u64 acc[8][2];
        {
            float4 bl = *(const float4*)&sm[O_B4 + oc0];
            float4 bh = *(const float4*)&sm[O_B4 + oc0 + 4];
            float bb[8] = {bl.x, bl.y, bl.z, bl.w, bh.x, bh.y, bh.z, bh.w};
            #pragma unroll
            for (int c = 0; c < 8; c++) {
                u64 bd = dup2(bb[c]);
                acc[c][0] = bd; acc[c][1] = bd;
            }
        }
        #pragma unroll 4
        for (int ic = 0; ic < 80; ic++) {
            ulonglong2 a = *(const ulonglong2*)&sm[O_X + ic * ST2 + x0];
            float4 w0 = *(const float4*)&sm[O_W4T + ic * 40 + oc0];
            float4 w1v = *(const float4*)&sm[O_W4T + ic * 40 + oc0 + 4];
            u64 dw[8] = {dup2(w0.x), dup2(w0.y), dup2(w0.z), dup2(w0.w),
                         dup2(w1v.x), dup2(w1v.y), dup2(w1v.z), dup2(w1v.w)};
            #pragma unroll
            for (int c = 0; c < 8; c++) {
                fma2(acc[c][0], dw[c], a.x);
                fma2(acc[c][1], dw[c], a.y);
            }
        }
        int p0 = o0 + 1 + x0;
        float m0 = (unsigned)(p0 + 0) < (unsigned)NTOT ? 1.f : 0.f;
        float m1 = (unsigned)(p0 + 1) < (unsigned)NTOT ? 1.f : 0.f;
        float m2 = (unsigned)(p0 + 2) < (unsigned)NTOT ? 1.f : 0.f;
        float m3 = (unsigned)(p0 + 3) < (unsigned)NTOT ? 1.f : 0.f;
        #pragma unroll
        for (int c = 0; c < 8; c++) {
            float f0, f1, f2, f3;
            unpack2(acc[c][0], f0, f1);
            unpack2(acc[c][1], f2, f3);
            *(float4*)&sm[O_Y + (oc0 + c) * ST2 + x0] =
                make_float4(m0 * eluf(f0), m1 * eluf(f1), m2 * eluf(f2), m3 * eluf(f3));
        }
    }
    // zero A4 tail slots (positions 260..271, read by conv5 windows at tile edge)
    for (int t = tid; t < 40; t += NTH) {
        float4 z = {0.f, 0.f, 0.f, 0.f};
        *(float4*)&sm[O_Y + t * ST2 + 260] = z;
        *(float4*)&sm[O_Y + t * ST2 + 264] = z;
        *(float4*)&sm[O_Y + t * ST2 + 268] = z;
    }
    __syncthreads();

    // ---- conv5: 40->20, k3 pad1.  oc-paired f32x2, C=2, P=8.  Y(A4)->X(A5), base o0+2 ----
    for (int t = tid; t < 10 * 33; t += NTH) {
        int ocg = t / 33, x0 = (t % 33) * 8;
        int oc0 = ocg * 2;
        u64 acc[8];
        {
            float2 bv = *(const float2*)&sm[O_B5 + oc0];
            u64 b = pack2(bv.x, bv.y);
            #pragma unroll
            for (int p = 0; p < 8; p++) acc[p] = b;
        }
        #pragma unroll 4
        for (int ic = 0; ic < 40; ic++) {
            const float* ar = &sm[O_Y + ic * ST2 + x0];
            float4 v0 = *(const float4*)(ar);
            float4 v1 = *(const float4*)(ar + 4);
            float2 v2 = *(const float2*)(ar + 8);
            u64 dwin[10] = {dup2(v0.x), dup2(v0.y), dup2(v0.z), dup2(v0.w),
                            dup2(v1.x), dup2(v1.y), dup2(v1.z), dup2(v1.w),
                            dup2(v2.x), dup2(v2.y)};
            #pragma unroll
            for (int k = 0; k < 3; k++) {
                u64 w = *(const u64*)&sm[O_W5T + (ic * 3 + k) * 20 + oc0];
                #pragma unroll
                for (int p = 0; p < 8; p++) fma2(acc[p], w, dwin[p + k]);
            }
        }
        float lo[8], hi[8];
        #pragma unroll
        for (int p = 0; p < 8; p++) unpack2(acc[p], lo[p], hi[p]);
        float* dA = &sm[O_X + (oc0 + 0) * ST2 + x0];
        float* dB = &sm[O_X + (oc0 + 1) * ST2 + x0];
        *(float4*)(dA)     = make_float4(eluf(lo[0]), eluf(lo[1]), eluf(lo[2]), eluf(lo[3]));
        *(float4*)(dA + 4) = make_float4(eluf(lo[4]), eluf(lo[5]), eluf(lo[6]), eluf(lo[7]));
        *(float4*)(dB)     = make_float4(eluf(hi[0]), eluf(hi[1]), eluf(hi[2]), eluf(hi[3]));
        *(float4*)(dB + 4) = make_float4(eluf(hi[4]), eluf(hi[5]), eluf(hi[6]), eluf(hi[7]));
    }
    __syncthreads();

    // ---- conv6 + sigmoid + bias: beta_mult, base o0+2, width TW+2 ----
    for (int x = tid; x < TW + 2; x += NTH) {
        float acc = sm[O_B6];
        #pragma unroll
        for (int c = 0; c < 20; c++) acc += sm[O_W6 + c] * sm[O_X + c * ST2 + x];
        sm[O_BM + x] = 1.f / (1.f + __expf(-acc)) + 0.1f;
    }
    __syncthreads();

    // ---- WENO5 flux ----
    int j = o0 + tid;
    if (tid < TW && j < NOUT) {
        const float* U = &sm[O_UU + tid + 5];   // uu[j+1 .. j+6]
        float v0 = U[0], v1 = U[1], v2 = U[2], v3 = U[3], v4 = U[4], v5 = U[5];
        float m0 = sm[O_BM + tid];
        float m1 = sm[O_BM + tid + 1];
        float m2 = sm[O_BM + tid + 2];
        float e = e_p[0];
        float fluxp = weno_side(v1, v2, v3, v4, v5, m0, m1, m2, e);
        float fluxn = weno_side(v0, v1, v2, v3, v4, m0, m1, m2, e);
        out[j] = fluxp - fluxn;
    }
}

extern "C" void kernel_launch(void* const* d_in, const int* in_sizes, int n_in,
                              void* d_out, int out_size) {
    const float* uu = (const float*)d_in[0];
    const float* e  = (const float*)d_in[1];
    const float* w1 = (const float*)d_in[2];
    const float* b1 = (const float*)d_in[3];
    const float* w2 = (const float*)d_in[4];
    const float* b2 = (const float*)d_in[5];
    const float* w3 = (const float*)d_in[6];
    const float* b3 = (const float*)d_in[7];
    const float* w4 = (const float*)d_in[8];
    const float* b4 = (const float*)d_in[9];
    const float* w5 = (const float*)d_in[10];
    const float* b5 = (const float*)d_in[11];
    const float* w6 = (const float*)d_in[12];
    const float* b6 = (const float*)d_in[13];
    float* out = (float*)d_out;

    cudaFuncSetAttribute(weno_fused, cudaFuncAttributeMaxDynamicSharedMemorySize, SMEM_BYTES);
    int grid = (NOUT + TW - 1) / TW;
    weno_fused<<<grid, NTH, SMEM_BYTES>>>(uu, e, w1, b1, w2, b2, w3, b3, w4, b4,
                                          w5, b5, w6, b6, out);
}

// round 8
// speedup vs baseline: 8.1905x; 1.0479x over previous
#include <cuda_runtime.h>
#include <math.h>

#define NTH 320
#define NWARP 10
#define TW  248           // outputs per block; row width 256 = 2 warp-spans

constexpr int NTOT = 2097152;
constexpr int NOUT = NTOT - 6;
constexpr int ST2  = 256;  // activation row stride (floats)

// ---- shared-memory weight offsets (floats); transposed oc-contiguous layouts ----
constexpr int O_W1  = 0;                 // 100   w1[oc][k]
constexpr int O_B1  = 100;               // 20
constexpr int O_W2T = 120;               // 4000  T2[(ic*5+k)*40 + oc]
constexpr int O_B2  = 4120;              // 40
constexpr int O_W3T = 4160;              // 3200  T3[ic*80 + oc]
constexpr int O_B3  = 7360;              // 80
constexpr int O_W4T = 7440;              // 3200  T4[ic*40 + oc]
constexpr int O_B4  = 10640;             // 40
constexpr int O_W5T = 10680;             // 2400  T5[(ic*3+k)*20 + oc]
constexpr int O_B5  = 13080;             // 20
constexpr int O_W6  = 13100;             // 20
constexpr int O_B6  = 13120;             // 1 (+3 pad)
// ---- activation area ----
constexpr int O_UU  = 13124;             // alloc 264 (need TW+14=262)
constexpr int O_DIF = O_UU + 264;        // alloc 264 (need TW+12=260)
constexpr int O_BM  = O_DIF + 264;       // alloc 256 (need TW+2=250)
constexpr int O_Y   = O_BM + 256;        // 40*ST2  (A2, A4)
constexpr int O_X   = O_Y + 40 * ST2;    // 80*ST2  (A1 rows 0-19, A3 all, A5 rows 0-19)
constexpr int SMEM_FLOATS = O_X + 80 * ST2;
constexpr int SMEM_BYTES  = SMEM_FLOATS * 4;   // ~178 KB

typedef unsigned long long u64;

__device__ __forceinline__ u64 dup2(float x) {
    u64 r;
    asm("mov.b64 %0, {%1, %1};" : "=l"(r) : "f"(x));
    return r;
}
__device__ __forceinline__ u64 pack2(float lo, float hi) {
    u64 r;
    asm("mov.b64 %0, {%1, %2};" : "=l"(r) : "f"(lo), "f"(hi));
    return r;
}
__device__ __forceinline__ void unpack2(u64 v, float& lo, float& hi) {
    asm("mov.b64 {%0, %1}, %2;" : "=f"(lo), "=f"(hi) : "l"(v));
}
__device__ __forceinline__ void fma2(u64& acc, u64 w, u64 a) {
    asm("fma.rn.f32x2 %0, %1, %2, %0;" : "+l"(acc) : "l"(w), "l"(a));
}

__device__ __forceinline__ float eluf(float x) {
    return x > 0.f ? x : (__expf(x) - 1.f);
}

__device__ __forceinline__ float weno_side(float u0, float u1, float u2, float u3, float u4,
                                           float m0, float m1, float m2, float e) {
    const float c16 = 1.f / 6.f;
    float f0 = (11.f * u2 - 7.f * u3 + 2.f * u4) * c16;
    float f1 = (2.f * u1 + 5.f * u2 - u3) * c16;
    float f2 = (-u0 + 5.f * u1 + 2.f * u2) * c16;
    float t, b0, b1, b2;
    t = u2 - 2.f * u3 + u4;          b0 = (13.f / 12.f) * t * t;
    t = 3.f * u2 - 4.f * u3 + u4;    b0 += 0.25f * t * t;
    t = u1 - 2.f * u2 + u3;          b1 = (13.f / 12.f) * t * t;
    t = u1 - u3;                     b1 += 0.25f * t * t;
    t = u0 - 2.f * u1 + u2;          b2 = (13.f / 12.f) * t * t;
    t = u0 - 4.f * u1 + 3.f * u2;    b2 += 0.25f * t * t;
    b0 *= m0; b1 *= m1; b2 *= m2;
    float brs = (b2 - b0) * (b2 - b0);
    float q0 = (e + b0) * (e + b0);
    float q1 = (e + b1) * (e + b1);
    float q2 = (e + b2) * (e + b2);
    float o0 = 0.1f / q0 * (brs + q0);
    float o1 = 0.6f / q1 * (brs + q1);
    float o2 = 0.3f / q2 * (brs + q2);
    float s = o0 + o1 + o2;
    return (o0 * f0 + o1 * f1 + o2 * f2) / s;
}

__global__ __launch_bounds__(NTH, 1)
void weno_fused(const float* __restrict__ uu, const float* __restrict__ e_p,
                const float* __restrict__ w1, const float* __restrict__ b1,
                const float* __restrict__ w2, const float* __restrict__ b2,
                const float* __restrict__ w3, const float* __restrict__ b3,
                const float* __restrict__ w4, const float* __restrict__ b4,
                const float* __restrict__ w5, const float* __restrict__ b5,
                const float* __restrict__ w6, const float* __restrict__ b6,
                float* __restrict__ out) {
    extern __shared__ float sm[];
    const int tid  = threadIdx.x;
    const int wid  = tid / 32;
    const int lane = tid % 32;
    const int o0 = blockIdx.x * TW;

    // ---- stage weights (transposed to oc-contiguous) ----
    for (int i = tid; i < 100;  i += NTH) sm[O_W1 + i] = w1[i];
    for (int i = tid; i < 20;   i += NTH) sm[O_B1 + i] = b1[i];
    for (int i = tid; i < 4000; i += NTH) {
        int oc = i / 100, r = i % 100;           // r = ic*5 + k
        sm[O_W2T + r * 40 + oc] = w2[i];
    }
    for (int i = tid; i < 40;   i += NTH) sm[O_B2 + i] = b2[i];
    for (int i = tid; i < 3200; i += NTH) {
        int oc = i / 40, ic = i % 40;
        sm[O_W3T + ic * 80 + oc] = w3[i];
    }
    for (int i = tid; i < 80;   i += NTH) sm[O_B3 + i] = b3[i];
    for (int i = tid; i < 3200; i += NTH) {
        int oc = i / 80, ic = i % 80;
        sm[O_W4T + ic * 40 + oc] = w4[i];
    }
    for (int i = tid; i < 40;   i += NTH) sm[O_B4 + i] = b4[i];
    for (int i = tid; i < 2400; i += NTH) {
        int oc = i / 120, r = i % 120;           // r = ic*3 + k
        sm[O_W5T + r * 20 + oc] = w5[i];
    }
    for (int i = tid; i < 20;   i += NTH) sm[O_B5 + i] = b5[i];
    for (int i = tid; i < 20;   i += NTH) sm[O_W6 + i] = w6[i];
    if (tid == 0) sm[O_B6] = b6[0];

    // ---- stage uu window [o0-4, o0+TW+10), index-clamped ----
    for (int i = tid; i < TW + 14; i += NTH) {
        int g = o0 - 4 + i;
        g = min(max(g, 0), NTOT - 1);
        sm[O_UU + i] = uu[g];
    }
    __syncthreads();

    // ---- dif window [o0-3, o0+TW+9); zero outside [0,N) ----
    for (int i = tid; i < TW + 12; i += NTH) {
        int gi = o0 - 3 + i;
        float v = 0.f;
        if ((unsigned)gi < (unsigned)NTOT) {
            int m1 = min(gi, NTOT - 2);
            int m2 = max(gi - 1, 0);
            int base = o0 - 4;
            v = 0.5f * ((sm[O_UU + m1 + 1 - base] - sm[O_UU + m1 - base]) +
                        (sm[O_UU + m2 + 1 - base] - sm[O_UU + m2 - base]));
        }
        sm[O_DIF + i] = v;
    }
    __syncthreads();

    // ---- conv1: 1->20, k5 pad2.  warp-contiguous, P=4.  A1 = X rows 0-19, base o0-1 ----
    for (int t = wid; t < 40; t += NWARP) {
        int c = t >> 1, s = t & 1;
        int x0 = 128 * s + 4 * lane;
        float bias = sm[O_B1 + c];
        float acc[4];
        #pragma unroll
        for (int p = 0; p < 4; p++) acc[p] = bias;
        float4 d0 = *(const float4*)&sm[O_DIF + x0];
        float4 d1 = *(const float4*)&sm[O_DIF + x0 + 4];
        float win[8] = {d0.x, d0.y, d0.z, d0.w, d1.x, d1.y, d1.z, d1.w};
        #pragma unroll
        for (int k = 0; k < 5; k++) {
            float w = sm[O_W1 + c * 5 + k];
            #pragma unroll
            for (int p = 0; p < 4; p++) acc[p] += w * win[p + k];
        }
        int pg = o0 - 1 + x0;
        float4 r;
        r.x = (unsigned)(pg + 0) < (unsigned)NTOT ? eluf(acc[0]) : 0.f;
        r.y = (unsigned)(pg + 1) < (unsigned)NTOT ? eluf(acc[1]) : 0.f;
        r.z = (unsigned)(pg + 2) < (unsigned)NTOT ? eluf(acc[2]) : 0.f;
        r.w = (unsigned)(pg + 3) < (unsigned)NTOT ? eluf(acc[3]) : 0.f;
        *(float4*)&sm[O_X + c * ST2 + x0] = r;
    }
    __syncthreads();

    // ---- conv2: 20->40, k5 pad2.  oc-paired f32x2, C=8, P=4.  X(A1)->Y(A2), base o0+1 ----
    for (int t = wid; t < 10; t += NWARP) {
        int ocg = t >> 1, s = t & 1;
        int oc0 = ocg * 8;
        int x0 = 128 * s + 4 * lane;
        u64 acc[4][4];   // [oc pair][pos]
        {
            float4 b0 = *(const float4*)&sm[O_B2 + oc0];
            float4 b1v = *(const float4*)&sm[O_B2 + oc0 + 4];
            u64 bp[4] = {pack2(b0.x, b0.y), pack2(b0.z, b0.w),
                         pack2(b1v.x, b1v.y), pack2(b1v.z, b1v.w)};
            #pragma unroll
            for (int j = 0; j < 4; j++)
                #pragma unroll
                for (int p = 0; p < 4; p++) acc[j][p] = bp[j];
        }
        #pragma unroll 2
        for (int ic = 0; ic < 20; ic++) {
            const float* ar = &sm[O_X + ic * ST2 + x0];
            float4 v0 = *(const float4*)(ar);
            float4 v1 = *(const float4*)(ar + 4);
            u64 dwin[8] = {dup2(v0.x), dup2(v0.y), dup2(v0.z), dup2(v0.w),
                           dup2(v1.x), dup2(v1.y), dup2(v1.z), dup2(v1.w)};
            #pragma unroll
            for (int k = 0; k < 5; k++) {
                ulonglong2 wA = *(const ulonglong2*)&sm[O_W2T + (ic * 5 + k) * 40 + oc0];
                ulonglong2 wB = *(const ulonglong2*)&sm[O_W2T + (ic * 5 + k) * 40 + oc0 + 4];
                #pragma unroll
                for (int p = 0; p < 4; p++) {
                    fma2(acc[0][p], wA.x, dwin[p + k]);
                    fma2(acc[1][p], wA.y, dwin[p + k]);
                    fma2(acc[2][p], wB.x, dwin[p + k]);
                    fma2(acc[3][p], wB.y, dwin[p + k]);
                }
            }
        }
        #pragma unroll
        for (int j = 0; j < 4; j++) {
            float lo[4], hi[4];
            #pragma unroll
            for (int p = 0; p < 4; p++) unpack2(acc[j][p], lo[p], hi[p]);
            *(float4*)&sm[O_Y + (oc0 + 2 * j) * ST2 + x0] =
                make_float4(eluf(lo[0]), eluf(lo[1]), eluf(lo[2]), eluf(lo[3]));
            *(float4*)&sm[O_Y + (oc0 + 2 * j + 1) * ST2 + x0] =
                make_float4(eluf(hi[0]), eluf(hi[1]), eluf(hi[2]), eluf(hi[3]));
        }
    }
    __syncthreads();

    // ---- conv3: 40->80, 1x1.  pos-packed f32x2, C=16, P=4.  Y(A2)->X(A3) ----
    for (int t = wid; t < 10; t += NWARP) {
        int ocg = t >> 1, s = t & 1;
        int oc0 = ocg * 16;
        int x0 = 128 * s + 4 * lane;
        u64 acc[16][2];
        {
            float bb[16];
            #pragma unroll
            for (int q = 0; q < 4; q++) {
                float4 b = *(const float4*)&sm[O_B3 + oc0 + 4 * q];
                bb[4 * q] = b.x; bb[4 * q + 1] = b.y; bb[4 * q + 2] = b.z; bb[4 * q + 3] = b.w;
            }
            #pragma unroll
            for (int c = 0; c < 16; c++) {
                u64 bd = dup2(bb[c]);
                acc[c][0] = bd; acc[c][1] = bd;
            }
        }
        #pragma unroll 2
        for (int ic = 0; ic < 40; ic++) {
            ulonglong2 a = *(const ulonglong2*)&sm[O_Y + ic * ST2 + x0];
            u64 dw[16];
            #pragma unroll
            for (int q = 0; q < 4; q++) {
                float4 w = *(const float4*)&sm[O_W3T + ic * 80 + oc0 + 4 * q];
                dw[4 * q] = dup2(w.x); dw[4 * q + 1] = dup2(w.y);
                dw[4 * q + 2] = dup2(w.z); dw[4 * q + 3] = dup2(w.w);
            }
            #pragma unroll
            for (int c = 0; c < 16; c++) {
                fma2(acc[c][0], dw[c], a.x);
                fma2(acc[c][1], dw[c], a.y);
            }
        }
        #pragma unroll
        for (int c = 0; c < 16; c++) {
            float f0, f1, f2, f3;
            unpack2(acc[c][0], f0, f1);
            unpack2(acc[c][1], f2, f3);
            *(float4*)&sm[O_X + (oc0 + c) * ST2 + x0] =
                make_float4(eluf(f0), eluf(f1), eluf(f2), eluf(f3));
        }
    }
    __syncthreads();

    // ---- conv4: 80->40, 1x1.  pos-packed f32x2, C=8, P=4.  X(A3)->Y(A4); zero outside [0,N) ----
    for (int t = wid; t < 10; t += NWARP) {
        int ocg = t >> 1, s = t & 1;
        int oc0 = ocg * 8;
        int x0 = 128 * s + 4 * lane;
        u64 acc[8][2];
        {
            float4 b0 = *(const float4*)&sm[O_B4 + oc0];
            float4 b1v = *(const float4*)&sm[O_B4 + oc0 + 4];
            float bb[8] = {b0.x, b0.y, b0.z, b0.w, b1v.x, b1v.y, b1v.z, b1v.w};
            #pragma unroll
            for (int c = 0; c < 8; c++) {
                u64 bd = dup2(bb[c]);
                acc[c][0] = bd; acc[c][1] = bd;
            }
        }
        #pragma unroll 2
        for (int ic = 0; ic < 80; ic++) {
            ulonglong2 a = *(const ulonglong2*)&sm[O_X + ic * ST2 + x0];
            float4 w0 = *(const float4*)&sm[O_W4T + ic * 40 + oc0];
            float4 w1v = *(const float4*)&sm[O_W4T + ic * 40 + oc0 + 4];
            u64 dw[8] = {dup2(w0.x), dup2(w0.y), dup2(w0.z), dup2(w0.w),
                         dup2(w1v.x), dup2(w1v.y), dup2(w1v.z), dup2(w1v.w)};
            #pragma unroll
            for (int c = 0; c < 8; c++) {
                fma2(acc[c][0], dw[c], a.x);
                fma2(acc[c][1], dw[c], a.y);
            }
        }
        int p0 = o0 + 1 + x0;
        float m0 = (unsigned)(p0 + 0) < (unsigned)NTOT ? 1.f : 0.f;
        float m1 = (unsigned)(p0 + 1) < (unsigned)NTOT ? 1.f : 0.f;
        float m2 = (unsigned)(p0 + 2) < (unsigned)NTOT ? 1.f : 0.f;
        float m3 = (unsigned)(p0 + 3) < (unsigned)NTOT ? 1.f : 0.f;
        #pragma unroll
        for (int c = 0; c < 8; c++) {
            float f0, f1, f2, f3;
            unpack2(acc[c][0], f0, f1);
            unpack2(acc[c][1], f2, f3);
            *(float4*)&sm[O_Y + (oc0 + c) * ST2 + x0] =
                make_float4(m0 * eluf(f0), m1 * eluf(f1), m2 * eluf(f2), m3 * eluf(f3));
        }
    }
    __syncthreads();

    // ---- conv5: 40->20, k3 pad1.  oc-paired f32x2, C=4, P=4.  Y(A4)->X(A5), base o0+2 ----
    for (int t = wid; t < 10; t += NWARP) {
        int ocg = t >> 1, s = t & 1;
        int oc0 = ocg * 4;
        int x0 = 128 * s + 4 * lane;
        u64 acc[2][4];
        {
            float4 bv = *(const float4*)&sm[O_B5 + oc0];
            u64 b01 = pack2(bv.x, bv.y), b23 = pack2(bv.z, bv.w);
            #pragma unroll
            for (int p = 0; p < 4; p++) { acc[0][p] = b01; acc[1][p] = b23; }
        }
        #pragma unroll 4
        for (int ic = 0; ic < 40; ic++) {
            const float* ar = &sm[O_Y + ic * ST2 + x0];
            float4 v0 = *(const float4*)(ar);
            float2 v1 = *(const float2*)(ar + 4);
            u64 dwin[6] = {dup2(v0.x), dup2(v0.y), dup2(v0.z), dup2(v0.w),
                           dup2(v1.x), dup2(v1.y)};
            #pragma unroll
            for (int k = 0; k < 3; k++) {
                ulonglong2 w = *(const ulonglong2*)&sm[O_W5T + (ic * 3 + k) * 20 + oc0];
                #pragma unroll
                for (int p = 0; p < 4; p++) {
                    fma2(acc[0][p], w.x, dwin[p + k]);
                    fma2(acc[1][p], w.y, dwin[p + k]);
                }
            }
        }
        #pragma unroll
        for (int j = 0; j < 2; j++) {
            float lo[4], hi[4];
            #pragma unroll
            for (int p = 0; p < 4; p++) unpack2(acc[j][p], lo[p], hi[p]);
            *(float4*)&sm[O_X + (oc0 + 2 * j) * ST2 + x0] =
                make_float4(eluf(lo[0]), eluf(lo[1]), eluf(lo[2]), eluf(lo[3]));
            *(float4*)&sm[O_X + (oc0 + 2 * j + 1) * ST2 + x0] =
                make_float4(eluf(hi[0]), eluf(hi[1]), eluf(hi[2]), eluf(hi[3]));
        }
    }
    __syncthreads();

    // ---- conv6 + sigmoid + bias: beta_mult, base o0+2, width TW+2 ----
    for (int x = tid; x < TW + 2; x += NTH) {
        float acc = sm[O_B6];
        #pragma unroll
        for (int c = 0; c < 20; c++) acc += sm[O_W6 + c] * sm[O_X + c * ST2 + x];
        sm[O_BM + x] = 1.f / (1.f + __expf(-acc)) + 0.1f;
    }
    __syncthreads();

    // ---- WENO5 flux ----
    int j = o0 + tid;
    if (tid < TW && j < NOUT) {
        const float* U = &sm[O_UU + tid + 5];   // uu[j+1 .. j+6]
        float v0 = U[0], v1 = U[1], v2 = U[2], v3 = U[3], v4 = U[4], v5 = U[5];
        float m0 = sm[O_BM + tid];
        float m1 = sm[O_BM + tid + 1];
        float m2 = sm[O_BM + tid + 2];
        float e = e_p[0];
        float fluxp = weno_side(v1, v2, v3, v4, v5, m0, m1, m2, e);
        float fluxn = weno_side(v0, v1, v2, v3, v4, m0, m1, m2, e);
        out[j] = fluxp - fluxn;
    }
}

extern "C" void kernel_launch(void* const* d_in, const int* in_sizes, int n_in,
                              void* d_out, int out_size) {
    const float* uu = (const float*)d_in[0];
    const float* e  = (const float*)d_in[1];
    const float* w1 = (const float*)d_in[2];
    const float* b1 = (const float*)d_in[3];
    const float* w2 = (const float*)d_in[4];
    const float* b2 = (const float*)d_in[5];
    const float* w3 = (const float*)d_in[6];
    const float* b3 = (const float*)d_in[7];
    const float* w4 = (const float*)d_in[8];
    const float* b4 = (const float*)d_in[9];
    const float* w5 = (const float*)d_in[10];
    const float* b5 = (const float*)d_in[11];
    const float* w6 = (const float*)d_in[12];
    const float* b6 = (const float*)d_in[13];
    float* out = (float*)d_out;

    cudaFuncSetAttribute(weno_fused, cudaFuncAttributeMaxDynamicSharedMemorySize, SMEM_BYTES);
    int grid = (NOUT + TW - 1) / TW;
    weno_fused<<<grid, NTH, SMEM_BYTES>>>(uu, e, w1, b1, w2, b2, w3, b3, w4, b4,
                                          w5, b5, w6, b6, out);
}